// round 9
// baseline (speedup 1.0000x reference)
#include <cuda_runtime.h>
#include <math.h>
#include <stdint.h>

#define B_    32
#define T_    512
#define FD_   256
#define NH_   1024
#define NC_   512
#define H4_   2048
#define NOUT_ 8
#define M_    (B_ * T_)

__device__ float g_bufA[(size_t)M_ * H4_];
__device__ float g_bufB[(size_t)M_ * H4_];
__device__ float g_bufC[(size_t)M_ * NH_];
__device__ float g_bufD[(size_t)M_ * NH_];
__device__ uint32_t g_hA[2 * B_ * NC_];
__device__ uint32_t g_hB[2 * B_ * NC_];
__device__ unsigned g_slots[128 * 64];   // one arrival slot per CTA, 256B apart
__device__ unsigned g_release;

__device__ __forceinline__ float warpSum(float v) {
#pragma unroll
    for (int o = 16; o > 0; o >>= 1) v += __shfl_xor_sync(0xffffffffu, v, o);
    return v;
}
__device__ __forceinline__ float warpMax(float v) {
#pragma unroll
    for (int o = 16; o > 0; o >>= 1) v = fmaxf(v, __shfl_xor_sync(0xffffffffu, v, o));
    return v;
}
__device__ __forceinline__ float blockSum(float v, float* sh) {
    int lane = threadIdx.x & 31, w = threadIdx.x >> 5;
    v = warpSum(v);
    if (lane == 0) sh[w] = v;
    __syncthreads();
    if (w == 0) {
        float r = (lane < 8) ? sh[lane] : 0.f;
        r = warpSum(r);
        if (lane == 0) sh[0] = r;
    }
    __syncthreads();
    float r = sh[0];
    __syncthreads();
    return r;
}
__device__ __forceinline__ float blockMax(float v, float* sh) {
    int lane = threadIdx.x & 31, w = threadIdx.x >> 5;
    v = warpMax(v);
    if (lane == 0) sh[w] = v;
    __syncthreads();
    if (w == 0) {
        float r = (lane < 8) ? sh[lane] : -3.0e38f;
        r = warpMax(r);
        if (lane == 0) sh[0] = r;
    }
    __syncthreads();
    float r = sh[0];
    __syncthreads();
    return r;
}

__device__ __forceinline__ uint32_t f2tf32(float f) {
    uint32_t r;
    asm("cvt.rna.tf32.f32 %0, %1;" : "=r"(r) : "f"(f));
    return r;
}

__device__ __forceinline__ void mma_tf32(float* c, const uint32_t* a, const uint32_t* b) {
    asm volatile(
        "mma.sync.aligned.m16n8k8.row.col.f32.tf32.tf32.f32 "
        "{%0,%1,%2,%3}, {%4,%5,%6,%7}, {%8,%9}, {%0,%1,%2,%3};"
        : "+f"(c[0]), "+f"(c[1]), "+f"(c[2]), "+f"(c[3])
        : "r"(a[0]), "r"(a[1]), "r"(a[2]), "r"(a[3]), "r"(b[0]), "r"(b[1]));
}

// ---- tf32 tensor-core GEMM with register-prefetch pipelining ----
// C[M,N] = A[M,K] @ W[N,K]^T + bias1 (+bias2)
__global__ __launch_bounds__(256) void gemm_tf32(
    const float* __restrict__ A, const float* __restrict__ W,
    float* __restrict__ C, const float* __restrict__ bias1,
    const float* __restrict__ bias2, int M, int N, int K)
{
    __shared__ uint32_t As[128][36];
    __shared__ uint32_t Bs[128][36];
    int tid = threadIdx.x;
    int lane = tid & 31, warp = tid >> 5;
    int wm = warp >> 2, wn = warp & 3;
    int lr = lane >> 2, lc = lane & 3;
    int bm = blockIdx.y * 128, bn = blockIdx.x * 128;

    int ldrow = tid >> 3;             // 0..31 (+32*i)
    int ldc4 = (tid & 7) << 2;

    float acc[4][4][4];
#pragma unroll
    for (int mt = 0; mt < 4; mt++)
#pragma unroll
        for (int nt = 0; nt < 4; nt++)
#pragma unroll
            for (int q = 0; q < 4; q++) acc[mt][nt][q] = 0.f;

    float4 a_pre[4], b_pre[4];
#pragma unroll
    for (int i = 0; i < 4; i++) {
        int row = ldrow + (i << 5);
        a_pre[i] = *(const float4*)(A + (size_t)(bm + row) * K + ldc4);
        b_pre[i] = *(const float4*)(W + (size_t)(bn + row) * K + ldc4);
    }

    for (int k0 = 0; k0 < K; k0 += 32) {
#pragma unroll
        for (int i = 0; i < 4; i++) {
            int row = ldrow + (i << 5);
            uint4 ta, tb;
            ta.x = f2tf32(a_pre[i].x); ta.y = f2tf32(a_pre[i].y);
            ta.z = f2tf32(a_pre[i].z); ta.w = f2tf32(a_pre[i].w);
            tb.x = f2tf32(b_pre[i].x); tb.y = f2tf32(b_pre[i].y);
            tb.z = f2tf32(b_pre[i].z); tb.w = f2tf32(b_pre[i].w);
            *(uint4*)&As[row][ldc4] = ta;
            *(uint4*)&Bs[row][ldc4] = tb;
        }
        __syncthreads();
        if (k0 + 32 < K) {
#pragma unroll
            for (int i = 0; i < 4; i++) {
                int row = ldrow + (i << 5);
                a_pre[i] = *(const float4*)(A + (size_t)(bm + row) * K + k0 + 32 + ldc4);
                b_pre[i] = *(const float4*)(W + (size_t)(bn + row) * K + k0 + 32 + ldc4);
            }
        }
#pragma unroll
        for (int ks = 0; ks < 4; ks++) {
            int kc = ks << 3;
            uint32_t af[4][4], bf[4][2];
#pragma unroll
            for (int mt = 0; mt < 4; mt++) {
                int rb = wm * 64 + mt * 16;
                af[mt][0] = As[rb + lr][kc + lc];
                af[mt][1] = As[rb + lr + 8][kc + lc];
                af[mt][2] = As[rb + lr][kc + lc + 4];
                af[mt][3] = As[rb + lr + 8][kc + lc + 4];
            }
#pragma unroll
            for (int nt = 0; nt < 4; nt++) {
                int nb = wn * 32 + nt * 8;
                bf[nt][0] = Bs[nb + lr][kc + lc];
                bf[nt][1] = Bs[nb + lr][kc + lc + 4];
            }
#pragma unroll
            for (int mt = 0; mt < 4; mt++)
#pragma unroll
                for (int nt = 0; nt < 4; nt++)
                    mma_tf32(acc[mt][nt], af[mt], bf[nt]);
        }
        __syncthreads();
    }

#pragma unroll
    for (int nt = 0; nt < 4; nt++) {
        int col = bn + wn * 32 + nt * 8 + (lc << 1);
        float b0 = bias1 ? bias1[col] : 0.f;
        float b1 = bias1 ? bias1[col + 1] : 0.f;
        if (bias2) { b0 += bias2[col]; b1 += bias2[col + 1]; }
#pragma unroll
        for (int mt = 0; mt < 4; mt++) {
            int row = bm + wm * 64 + mt * 16 + lr;
            float2 v0 = make_float2(acc[mt][nt][0] + b0, acc[mt][nt][1] + b1);
            float2 v1 = make_float2(acc[mt][nt][2] + b0, acc[mt][nt][3] + b1);
            *(float2*)(C + (size_t)row * N + col) = v0;
            *(float2*)(C + (size_t)(row + 8) * N + col) = v1;
        }
    }
}

// LayerNorm + LeakyReLU (+ pad-mask zero) in place
__global__ __launch_bounds__(256) void ln_lrelu(
    float* __restrict__ X, const float* __restrict__ g,
    const float* __restrict__ be, const int* __restrict__ lens)
{
    __shared__ float sh[8];
    int row = blockIdx.x;
    float* x = X + (size_t)row * NH_;
    int tid = threadIdx.x;
    float v[4], s = 0.f, ss = 0.f;
#pragma unroll
    for (int i = 0; i < 4; i++) {
        float t = x[tid + (i << 8)];
        v[i] = t; s += t; ss += t * t;
    }
    float S = blockSum(s, sh);
    float SS = blockSum(ss, sh);
    float mean = S * (1.f / NH_);
    float inv = rsqrtf(SS * (1.f / NH_) - mean * mean + 1e-5f);
    bool z = false;
    if (lens) z = ((row & (T_ - 1)) >= lens[row >> 9]);
#pragma unroll
    for (int i = 0; i < 4; i++) {
        int c = tid + (i << 8);
        float y = (v[i] - mean) * inv * g[c] + be[c];
        y = (y >= 0.f) ? y : 0.01f * y;
        x[c] = z ? 0.f : y;
    }
}

__global__ void zero_slots() {
    int i = blockIdx.x * blockDim.x + threadIdx.x;
    if (i < 128 * 64) g_slots[i] = 0u;
    if (i == 0) g_release = 0u;
}

// ---- persistent bidirectional LSTM layer, tensor-core recurrence ----
// 128 CTAs = 2 dirs x 64 chunks (8 hidden cols each), 128 threads (4 warps = 4 gates).
// h stored in global as tf32 bits, k-permuted so fragment pairs (k, k+4) are adjacent.
// Grid barrier: distributed arrival slots + CTA0 sweep + single release word.
#define LS_STRIDE 520
#define LS_H_OFF  (32 * LS_STRIDE)
#define LS_G_OFF  (64 * LS_STRIDE)
#define LSTM_SMEM ((64 * LS_STRIDE + 4 * 32 * 8) * 4)

__global__ __launch_bounds__(128) void lstm_layer(
    const float* __restrict__ xpf, const float* __restrict__ xpb,
    const float* __restrict__ whh,
    uint32_t* __restrict__ hA, uint32_t* __restrict__ hB,
    float* __restrict__ hcat)
{
    extern __shared__ float sm[];
    uint32_t* Wsm = (uint32_t*)sm;                  // [32 n][520] tf32, k-permuted
    uint32_t* hsp = (uint32_t*)(sm + LS_H_OFF);     // [32 b][520] tf32, k-permuted
    float*    gsm = sm + LS_G_OFF;                  // [4 gate][32 b][8 jj]

    int dir = blockIdx.x >> 6;
    int j0 = (blockIdx.x & 63) << 3;
    const float* xp = dir ? xpb : xpf;
    const float* W = whh + (size_t)dir * H4_ * NC_;
    int tid = threadIdx.x;
    int w = tid >> 5, lane = tid & 31;
    int lr = lane >> 2, lc = lane & 3;

    // cache + convert + permute whh slice (32 gate-cols x 512 k)
    for (int f = tid; f < 32 * 512; f += 128) {
        int n = f >> 9, k = f & 511;
        int g_ = n >> 3, jj = n & 7;
        float wv = W[(size_t)(g_ * NC_ + j0 + jj) * NC_ + k];
        int kp = (k & ~7) | ((k & 3) << 1) | ((k >> 2) & 1);
        Wsm[n * LS_STRIDE + kp] = f2tf32(wv);
    }
    __syncthreads();

    float creg[2] = {0.f, 0.f};

    const uint32_t* hr0 = hsp + lr * LS_STRIDE + 2 * lc;
    const uint32_t* wb  = Wsm + (w * 8 + lr) * LS_STRIDE + 2 * lc;
    size_t xcol = (size_t)w * NC_ + j0 + 2 * lc;

    for (int s = 0; s < T_; ++s) {
        int t = dir ? (T_ - 1 - s) : s;
        // prefetch xp early (independent of h)
        float2 x0, x1, x2, x3;
        {
            size_t tb = (size_t)t * H4_ + xcol;
            x0 = *(const float2*)(xp + ((size_t)(lr)      * T_) * H4_ + tb);
            x1 = *(const float2*)(xp + ((size_t)(lr + 8)  * T_) * H4_ + tb);
            x2 = *(const float2*)(xp + ((size_t)(lr + 16) * T_) * H4_ + tb);
            x3 = *(const float2*)(xp + ((size_t)(lr + 24) * T_) * H4_ + tb);
        }
        float a0a[4] = {0,0,0,0}, a0b[4] = {0,0,0,0};
        float a1a[4] = {0,0,0,0}, a1b[4] = {0,0,0,0};
        if (s > 0) {
            const uint32_t* hin = ((s & 1) ? hB : hA) + dir * B_ * NC_;
            // stage full h tile (already tf32 + permuted) 32x512
#pragma unroll
            for (int i = 0; i < 32; i++) {
                uint4 v = *(const uint4*)(hin + i * NC_ + tid * 4);
                *(uint4*)(hsp + i * LS_STRIDE + tid * 4) = v;
            }
            __syncthreads();
#pragma unroll 4
            for (int kc = 0; kc < 512; kc += 16) {
                uint2 p0 = *(const uint2*)(hr0 + kc);
                uint2 p1 = *(const uint2*)(hr0 + 8 * LS_STRIDE + kc);
                uint2 p2 = *(const uint2*)(hr0 + 16 * LS_STRIDE + kc);
                uint2 p3 = *(const uint2*)(hr0 + 24 * LS_STRIDE + kc);
                uint2 bv = *(const uint2*)(wb + kc);
                uint32_t A0[4] = {p0.x, p1.x, p0.y, p1.y};
                uint32_t A1[4] = {p2.x, p3.x, p2.y, p3.y};
                uint32_t Bf[2] = {bv.x, bv.y};
                mma_tf32(a0a, A0, Bf);
                mma_tf32(a1a, A1, Bf);
                uint2 q0 = *(const uint2*)(hr0 + kc + 8);
                uint2 q1 = *(const uint2*)(hr0 + 8 * LS_STRIDE + kc + 8);
                uint2 q2 = *(const uint2*)(hr0 + 16 * LS_STRIDE + kc + 8);
                uint2 q3 = *(const uint2*)(hr0 + 24 * LS_STRIDE + kc + 8);
                uint2 bw = *(const uint2*)(wb + kc + 8);
                uint32_t A0b[4] = {q0.x, q1.x, q0.y, q1.y};
                uint32_t A1b[4] = {q2.x, q3.x, q2.y, q3.y};
                uint32_t Bg[2] = {bw.x, bw.y};
                mma_tf32(a0b, A0b, Bg);
                mma_tf32(a1b, A1b, Bg);
            }
        }
        // merge chains + add xp, write gates to smem
        {
            float* gw = gsm + w * 256;
            *(float2*)(gw + lr * 8 + 2 * lc) =
                make_float2(a0a[0] + a0b[0] + x0.x, a0a[1] + a0b[1] + x0.y);
            *(float2*)(gw + (lr + 8) * 8 + 2 * lc) =
                make_float2(a0a[2] + a0b[2] + x1.x, a0a[3] + a0b[3] + x1.y);
            *(float2*)(gw + (lr + 16) * 8 + 2 * lc) =
                make_float2(a1a[0] + a1b[0] + x2.x, a1a[1] + a1b[1] + x2.y);
            *(float2*)(gw + (lr + 24) * 8 + 2 * lc) =
                make_float2(a1a[2] + a1b[2] + x3.x, a1a[3] + a1b[3] + x3.y);
        }
        __syncthreads();

        uint32_t* hout = ((s & 1) ? hA : hB) + dir * B_ * NC_;
#pragma unroll
        for (int r = 0; r < 2; r++) {
            int e = tid + (r << 7);
            int b = e >> 3, jj = e & 7;
            float gi = gsm[b * 8 + jj];
            float gf = gsm[256 + b * 8 + jj];
            float gg = gsm[512 + b * 8 + jj];
            float go = gsm[768 + b * 8 + jj];
            float fi = 1.f / (1.f + expf(-gi));
            float ff = 1.f / (1.f + expf(-gf));
            float fo = 1.f / (1.f + expf(-go));
            float cn = ff * creg[r] + fi * tanhf(gg);
            float hv = fo * tanhf(cn);
            creg[r] = cn;
            int kp = j0 + (((jj & 3) << 1) | (jj >> 2));
            hout[b * NC_ + kp] = f2tf32(hv);
            hcat[((size_t)b * T_ + t) * NH_ + dir * NC_ + j0 + jj] = hv;
        }
        __syncthreads();   // all CTA writes done before arrival signal

        // distributed grid barrier: per-CTA slot + CTA0 sweep + release word
        unsigned tgt = (unsigned)s + 1u;
        if (tid == 0) {
            __threadfence();
            *(volatile unsigned*)&g_slots[blockIdx.x * 64] = tgt;
        }
        if (blockIdx.x == 0) {
            if (tid < 32) {
                bool done = false;
                while (!done) {
                    unsigned mn = 0xffffffffu;
#pragma unroll
                    for (int q = 0; q < 4; q++) {
                        unsigned v = *(volatile unsigned*)&g_slots[(tid * 4 + q) * 64];
                        mn = min(mn, v);
                    }
                    done = __all_sync(0xffffffffu, mn >= tgt);
                }
                __threadfence();
                if (tid == 0) *(volatile unsigned*)&g_release = tgt;
            }
        } else {
            if (tid == 0) {
                while (*(volatile unsigned*)&g_release < tgt) { }
                __threadfence();
            }
        }
        __syncthreads();
    }
}

// attention pool + classifier, one CTA per batch
__global__ __launch_bounds__(256) void attn_out(
    const float* __restrict__ H, const int* __restrict__ lens,
    const float* __restrict__ w_u, const float* __restrict__ b_u,
    const float* __restrict__ Wc, const float* __restrict__ bc,
    float* __restrict__ out)
{
    __shared__ float sc[T_];
    __shared__ float pooled[NH_];
    __shared__ float red[8];
    int b = blockIdx.x;
    int tid = threadIdx.x, lane = tid & 31, w = tid >> 5;
    int len = lens[b];
    const float* Hb = H + (size_t)b * T_ * NH_;

    for (int t = w; t < T_; t += 8) {
        const float* hp = Hb + (size_t)t * NH_;
        float s = 0.f;
        for (int d = lane; d < NH_; d += 32) s += hp[d] * w_u[d];
        s = warpSum(s);
        if (lane == 0) sc[t] = s + b_u[0];
    }
    __syncthreads();

    float m = -3.0e38f;
    for (int t = tid; t < len; t += 256) m = fmaxf(m, sc[t]);
    m = blockMax(m, red);

    float ps = 0.f;
    for (int t = tid; t < T_; t += 256) {
        float e = (t < len) ? expf(sc[t] - m) : 0.f;
        sc[t] = e; ps += e;
    }
    float S = blockSum(ps, red);
    float inv = 1.f / S;

    {
        float a0 = 0.f, a1 = 0.f, a2 = 0.f, a3 = 0.f;
        for (int t = 0; t < len; ++t) {
            float al = sc[t];
            const float* hp = Hb + (size_t)t * NH_ + tid;
            a0 += al * hp[0];
            a1 += al * hp[256];
            a2 += al * hp[512];
            a3 += al * hp[768];
        }
        pooled[tid]       = a0 * inv;
        pooled[tid + 256] = a1 * inv;
        pooled[tid + 512] = a2 * inv;
        pooled[tid + 768] = a3 * inv;
    }
    __syncthreads();

    {
        const float* wc = Wc + (size_t)w * NH_;
        float s = 0.f;
        for (int d = lane; d < NH_; d += 32) s += pooled[d] * wc[d];
        s = warpSum(s);
        if (lane == 0) out[b * NOUT_ + w] = s + bc[w];
    }
}

extern "C" void kernel_launch(void* const* d_in, const int* in_sizes, int n_in,
                              void* d_out, int out_size)
{
    const float* x    = (const float*)d_in[0];
    const int*   lens = (const int*)d_in[1];
    const float* W1   = (const float*)d_in[2];
    const float* b1   = (const float*)d_in[3];
    const float* g1   = (const float*)d_in[4];
    const float* be1  = (const float*)d_in[5];
    const float* W2   = (const float*)d_in[6];
    const float* b2   = (const float*)d_in[7];
    const float* g2   = (const float*)d_in[8];
    const float* be2  = (const float*)d_in[9];
    const float* wih  = (const float*)d_in[10];
    const float* whh  = (const float*)d_in[11];
    const float* bih  = (const float*)d_in[12];
    const float* bhh  = (const float*)d_in[13];
    const float* w_u  = (const float*)d_in[14];
    const float* b_u  = (const float*)d_in[15];
    const float* Wc   = (const float*)d_in[16];
    const float* bc   = (const float*)d_in[17];
    float* out = (float*)d_out;
    (void)in_sizes; (void)n_in; (void)out_size;

    float *bufA, *bufB, *bufC, *bufD;
    uint32_t *hA, *hB;
    cudaGetSymbolAddress((void**)&bufA, g_bufA);
    cudaGetSymbolAddress((void**)&bufB, g_bufB);
    cudaGetSymbolAddress((void**)&bufC, g_bufC);
    cudaGetSymbolAddress((void**)&bufD, g_bufD);
    cudaGetSymbolAddress((void**)&hA, g_hA);
    cudaGetSymbolAddress((void**)&hB, g_hB);

    cudaFuncSetAttribute(lstm_layer, cudaFuncAttributeMaxDynamicSharedMemorySize,
                         LSTM_SMEM);

    dim3 blk(256);
    dim3 gMLP(NH_ / 128, M_ / 128);
    dim3 gXP(H4_ / 128, M_ / 128);

    gemm_tf32<<<gMLP, blk>>>(x, W1, bufD, b1, nullptr, M_, NH_, FD_);
    ln_lrelu<<<M_, blk>>>(bufD, g1, be1, nullptr);
    gemm_tf32<<<gMLP, blk>>>(bufD, W2, bufC, b2, nullptr, M_, NH_, NH_);
    ln_lrelu<<<M_, blk>>>(bufC, g2, be2, lens);

    for (int layer = 0; layer < 2; ++layer) {
        const float* inbuf = (layer == 0) ? bufC : bufD;
        float* hcat = (layer == 0) ? bufD : bufC;
        size_t wo = (size_t)layer * 2 * H4_ * NH_;
        size_t ho = (size_t)layer * 2 * H4_ * NC_;
        size_t bo = (size_t)layer * 2 * H4_;

        gemm_tf32<<<gXP, blk>>>(inbuf, wih + wo, bufA,
                                bih + bo, bhh + bo, M_, H4_, NH_);
        gemm_tf32<<<gXP, blk>>>(inbuf, wih + wo + (size_t)H4_ * NH_, bufB,
                                bih + bo + H4_, bhh + bo + H4_, M_, H4_, NH_);

        zero_slots<<<32, 256>>>();
        lstm_layer<<<128, 128, LSTM_SMEM>>>(bufA, bufB, whh + ho, hA, hB, hcat);
    }

    attn_out<<<B_, blk>>>(bufC, lens, w_u, b_u, Wc, bc, out);
}

// round 10
// speedup vs baseline: 1.0477x; 1.0477x over previous
#include <cuda_runtime.h>
#include <math.h>
#include <stdint.h>

#define B_    32
#define T_    512
#define FD_   256
#define NH_   1024
#define NC_   512
#define H4_   2048
#define NOUT_ 8
#define M_    (B_ * T_)

__device__ float g_bufA[(size_t)M_ * H4_];
__device__ float g_bufB[(size_t)M_ * H4_];
__device__ float g_bufC[(size_t)M_ * NH_];
__device__ float g_bufD[(size_t)M_ * NH_];
__device__ uint32_t g_hA[2 * B_ * NC_];
__device__ uint32_t g_hB[2 * B_ * NC_];
__device__ unsigned g_barc[2 * 64];   // per-dir arrival counters, 256B apart
__device__ unsigned g_bars[2 * 64];   // per-dir sense words, 256B apart

__device__ __forceinline__ float warpSum(float v) {
#pragma unroll
    for (int o = 16; o > 0; o >>= 1) v += __shfl_xor_sync(0xffffffffu, v, o);
    return v;
}
__device__ __forceinline__ float warpMax(float v) {
#pragma unroll
    for (int o = 16; o > 0; o >>= 1) v = fmaxf(v, __shfl_xor_sync(0xffffffffu, v, o));
    return v;
}
__device__ __forceinline__ float blockSum(float v, float* sh) {
    int lane = threadIdx.x & 31, w = threadIdx.x >> 5;
    v = warpSum(v);
    if (lane == 0) sh[w] = v;
    __syncthreads();
    if (w == 0) {
        float r = (lane < 8) ? sh[lane] : 0.f;
        r = warpSum(r);
        if (lane == 0) sh[0] = r;
    }
    __syncthreads();
    float r = sh[0];
    __syncthreads();
    return r;
}
__device__ __forceinline__ float blockMax(float v, float* sh) {
    int lane = threadIdx.x & 31, w = threadIdx.x >> 5;
    v = warpMax(v);
    if (lane == 0) sh[w] = v;
    __syncthreads();
    if (w == 0) {
        float r = (lane < 8) ? sh[lane] : -3.0e38f;
        r = warpMax(r);
        if (lane == 0) sh[0] = r;
    }
    __syncthreads();
    float r = sh[0];
    __syncthreads();
    return r;
}

__device__ __forceinline__ uint32_t f2tf32(float f) {
    uint32_t r;
    asm("cvt.rna.tf32.f32 %0, %1;" : "=r"(r) : "f"(f));
    return r;
}

__device__ __forceinline__ void mma_tf32(float* c, const uint32_t* a, const uint32_t* b) {
    asm volatile(
        "mma.sync.aligned.m16n8k8.row.col.f32.tf32.tf32.f32 "
        "{%0,%1,%2,%3}, {%4,%5,%6,%7}, {%8,%9}, {%0,%1,%2,%3};"
        : "+f"(c[0]), "+f"(c[1]), "+f"(c[2]), "+f"(c[3])
        : "r"(a[0]), "r"(a[1]), "r"(a[2]), "r"(a[3]), "r"(b[0]), "r"(b[1]));
}

// ---- tf32 tensor-core GEMM (R8 version): C[M,N] = A[M,K] @ W[N,K]^T + bias1 (+bias2) ----
__global__ __launch_bounds__(256) void gemm_tf32(
    const float* __restrict__ A, const float* __restrict__ W,
    float* __restrict__ C, const float* __restrict__ bias1,
    const float* __restrict__ bias2, int M, int N, int K)
{
    __shared__ uint32_t As[128][36];
    __shared__ uint32_t Bs[128][36];
    int tid = threadIdx.x;
    int lane = tid & 31, warp = tid >> 5;
    int wm = warp >> 2, wn = warp & 3;
    int lr = lane >> 2, lc = lane & 3;
    int bm = blockIdx.y * 128, bn = blockIdx.x * 128;

    float acc[4][4][4];
#pragma unroll
    for (int mt = 0; mt < 4; mt++)
#pragma unroll
        for (int nt = 0; nt < 4; nt++)
#pragma unroll
            for (int q = 0; q < 4; q++) acc[mt][nt][q] = 0.f;

    for (int k0 = 0; k0 < K; k0 += 32) {
#pragma unroll
        for (int i = 0; i < 4; i++) {
            int f = tid + (i << 8);
            int row = f >> 3, c4 = (f & 7) << 2;
            float4 a4 = *(const float4*)(A + (size_t)(bm + row) * K + k0 + c4);
            float4 b4 = *(const float4*)(W + (size_t)(bn + row) * K + k0 + c4);
            uint4 ta, tb;
            ta.x = f2tf32(a4.x); ta.y = f2tf32(a4.y);
            ta.z = f2tf32(a4.z); ta.w = f2tf32(a4.w);
            tb.x = f2tf32(b4.x); tb.y = f2tf32(b4.y);
            tb.z = f2tf32(b4.z); tb.w = f2tf32(b4.w);
            *(uint4*)&As[row][c4] = ta;
            *(uint4*)&Bs[row][c4] = tb;
        }
        __syncthreads();
#pragma unroll
        for (int ks = 0; ks < 4; ks++) {
            int kc = ks << 3;
            uint32_t af[4][4], bf[4][2];
#pragma unroll
            for (int mt = 0; mt < 4; mt++) {
                int rb = wm * 64 + mt * 16;
                af[mt][0] = As[rb + lr][kc + lc];
                af[mt][1] = As[rb + lr + 8][kc + lc];
                af[mt][2] = As[rb + lr][kc + lc + 4];
                af[mt][3] = As[rb + lr + 8][kc + lc + 4];
            }
#pragma unroll
            for (int nt = 0; nt < 4; nt++) {
                int nb = wn * 32 + nt * 8;
                bf[nt][0] = Bs[nb + lr][kc + lc];
                bf[nt][1] = Bs[nb + lr][kc + lc + 4];
            }
#pragma unroll
            for (int mt = 0; mt < 4; mt++)
#pragma unroll
                for (int nt = 0; nt < 4; nt++)
                    mma_tf32(acc[mt][nt], af[mt], bf[nt]);
        }
        __syncthreads();
    }

#pragma unroll
    for (int nt = 0; nt < 4; nt++) {
        int col = bn + wn * 32 + nt * 8 + (lc << 1);
        float b0 = bias1 ? bias1[col] : 0.f;
        float b1 = bias1 ? bias1[col + 1] : 0.f;
        if (bias2) { b0 += bias2[col]; b1 += bias2[col + 1]; }
#pragma unroll
        for (int mt = 0; mt < 4; mt++) {
            int row = bm + wm * 64 + mt * 16 + lr;
            float2 v0 = make_float2(acc[mt][nt][0] + b0, acc[mt][nt][1] + b1);
            float2 v1 = make_float2(acc[mt][nt][2] + b0, acc[mt][nt][3] + b1);
            *(float2*)(C + (size_t)row * N + col) = v0;
            *(float2*)(C + (size_t)(row + 8) * N + col) = v1;
        }
    }
}

// LayerNorm + LeakyReLU (+ pad-mask zero) in place
__global__ __launch_bounds__(256) void ln_lrelu(
    float* __restrict__ X, const float* __restrict__ g,
    const float* __restrict__ be, const int* __restrict__ lens)
{
    __shared__ float sh[8];
    int row = blockIdx.x;
    float* x = X + (size_t)row * NH_;
    int tid = threadIdx.x;
    float v[4], s = 0.f, ss = 0.f;
#pragma unroll
    for (int i = 0; i < 4; i++) {
        float t = x[tid + (i << 8)];
        v[i] = t; s += t; ss += t * t;
    }
    float S = blockSum(s, sh);
    float SS = blockSum(ss, sh);
    float mean = S * (1.f / NH_);
    float inv = rsqrtf(SS * (1.f / NH_) - mean * mean + 1e-5f);
    bool z = false;
    if (lens) z = ((row & (T_ - 1)) >= lens[row >> 9]);
#pragma unroll
    for (int i = 0; i < 4; i++) {
        int c = tid + (i << 8);
        float y = (v[i] - mean) * inv * g[c] + be[c];
        y = (y >= 0.f) ? y : 0.01f * y;
        x[c] = z ? 0.f : y;
    }
}

// ---- persistent bidirectional LSTM layer, tensor-core recurrence ----
// 128 CTAs = 2 dirs x 64 chunks (8 hidden cols each), 128 threads (4 warps = 4 gates).
// h stored in global as tf32 bits, k-permuted so fragment pairs (k, k+4) are adjacent.
// Per-direction atomic barrier (64 arrivals each, separate L2 lines).
#define LS_STRIDE 520
#define LS_H_OFF  (32 * LS_STRIDE)
#define LS_G_OFF  (64 * LS_STRIDE)
#define LSTM_SMEM ((64 * LS_STRIDE + 4 * 32 * 8) * 4)

__global__ __launch_bounds__(128) void lstm_layer(
    const float* __restrict__ xpf, const float* __restrict__ xpb,
    const float* __restrict__ whh,
    uint32_t* __restrict__ hA, uint32_t* __restrict__ hB,
    float* __restrict__ hcat)
{
    extern __shared__ float sm[];
    uint32_t* Wsm = (uint32_t*)sm;                  // [32 n][520] tf32, k-permuted
    uint32_t* hsp = (uint32_t*)(sm + LS_H_OFF);     // [32 b][520] tf32, k-permuted
    float*    gsm = sm + LS_G_OFF;                  // [4 gate][32 b][8 jj]
    __shared__ unsigned sh_base;

    int dir = blockIdx.x >> 6;
    int j0 = (blockIdx.x & 63) << 3;
    const float* xp = dir ? xpb : xpf;
    const float* W = whh + (size_t)dir * H4_ * NC_;
    unsigned* barc = &g_barc[dir * 64];
    unsigned* bars = &g_bars[dir * 64];
    int tid = threadIdx.x;
    int w = tid >> 5, lane = tid & 31;
    int lr = lane >> 2, lc = lane & 3;

    // cache + convert + permute whh slice (32 gate-cols x 512 k)
    for (int f = tid; f < 32 * 512; f += 128) {
        int n = f >> 9, k = f & 511;
        int g_ = n >> 3, jj = n & 7;
        float wv = W[(size_t)(g_ * NC_ + j0 + jj) * NC_ + k];
        int kp = (k & ~7) | ((k & 3) << 1) | ((k >> 2) & 1);
        Wsm[n * LS_STRIDE + kp] = f2tf32(wv);
    }
    if (tid == 0) sh_base = *(volatile unsigned*)bars;
    __syncthreads();
    unsigned base = sh_base;

    float creg[2] = {0.f, 0.f};

    const uint32_t* hr0 = hsp + lr * LS_STRIDE + 2 * lc;
    const uint32_t* wb  = Wsm + (w * 8 + lr) * LS_STRIDE + 2 * lc;
    size_t xcol = (size_t)w * NC_ + j0 + 2 * lc;

    // prefetch xp for step 0
    float2 x0, x1, x2, x3;
    {
        int t0 = dir ? (T_ - 1) : 0;
        size_t tb = (size_t)t0 * H4_ + xcol;
        x0 = *(const float2*)(xp + ((size_t)(lr)      * T_) * H4_ + tb);
        x1 = *(const float2*)(xp + ((size_t)(lr + 8)  * T_) * H4_ + tb);
        x2 = *(const float2*)(xp + ((size_t)(lr + 16) * T_) * H4_ + tb);
        x3 = *(const float2*)(xp + ((size_t)(lr + 24) * T_) * H4_ + tb);
    }

    for (int s = 0; s < T_; ++s) {
        int t = dir ? (T_ - 1 - s) : s;
        float a0a[4] = {0,0,0,0}, a0b[4] = {0,0,0,0};
        float a1a[4] = {0,0,0,0}, a1b[4] = {0,0,0,0};
        if (s > 0) {
            const uint32_t* hin = ((s & 1) ? hB : hA) + dir * B_ * NC_;
            // stage full h tile via cp.async (already tf32 + permuted), 32x512
#pragma unroll
            for (int i = 0; i < 32; i++) {
                uint32_t dst = (uint32_t)__cvta_generic_to_shared(
                    hsp + i * LS_STRIDE + tid * 4);
                asm volatile("cp.async.cg.shared.global [%0], [%1], 16;"
                             :: "r"(dst), "l"(hin + i * NC_ + tid * 4));
            }
            asm volatile("cp.async.commit_group;");
            asm volatile("cp.async.wait_group 0;" ::: "memory");
            __syncthreads();
#pragma unroll 4
            for (int kc = 0; kc < 512; kc += 16) {
                uint2 p0 = *(const uint2*)(hr0 + kc);
                uint2 p1 = *(const uint2*)(hr0 + 8 * LS_STRIDE + kc);
                uint2 p2 = *(const uint2*)(hr0 + 16 * LS_STRIDE + kc);
                uint2 p3 = *(const uint2*)(hr0 + 24 * LS_STRIDE + kc);
                uint2 bv = *(const uint2*)(wb + kc);
                uint32_t A0[4] = {p0.x, p1.x, p0.y, p1.y};
                uint32_t A1[4] = {p2.x, p3.x, p2.y, p3.y};
                uint32_t Bf[2] = {bv.x, bv.y};
                mma_tf32(a0a, A0, Bf);
                mma_tf32(a1a, A1, Bf);
                uint2 q0 = *(const uint2*)(hr0 + kc + 8);
                uint2 q1 = *(const uint2*)(hr0 + 8 * LS_STRIDE + kc + 8);
                uint2 q2 = *(const uint2*)(hr0 + 16 * LS_STRIDE + kc + 8);
                uint2 q3 = *(const uint2*)(hr0 + 24 * LS_STRIDE + kc + 8);
                uint2 bw = *(const uint2*)(wb + kc + 8);
                uint32_t A0b[4] = {q0.x, q1.x, q0.y, q1.y};
                uint32_t A1b[4] = {q2.x, q3.x, q2.y, q3.y};
                uint32_t Bg[2] = {bw.x, bw.y};
                mma_tf32(a0b, A0b, Bg);
                mma_tf32(a1b, A1b, Bg);
            }
        }
        // merge chains + add xp, write gates to smem
        {
            float* gw = gsm + w * 256;
            *(float2*)(gw + lr * 8 + 2 * lc) =
                make_float2(a0a[0] + a0b[0] + x0.x, a0a[1] + a0b[1] + x0.y);
            *(float2*)(gw + (lr + 8) * 8 + 2 * lc) =
                make_float2(a0a[2] + a0b[2] + x1.x, a0a[3] + a0b[3] + x1.y);
            *(float2*)(gw + (lr + 16) * 8 + 2 * lc) =
                make_float2(a1a[0] + a1b[0] + x2.x, a1a[1] + a1b[1] + x2.y);
            *(float2*)(gw + (lr + 24) * 8 + 2 * lc) =
                make_float2(a1a[2] + a1b[2] + x3.x, a1a[3] + a1b[3] + x3.y);
        }
        __syncthreads();

        uint32_t* hout = ((s & 1) ? hA : hB) + dir * B_ * NC_;
#pragma unroll
        for (int r = 0; r < 2; r++) {
            int e = tid + (r << 7);
            int b = e >> 3, jj = e & 7;
            float gi = gsm[b * 8 + jj];
            float gf = gsm[256 + b * 8 + jj];
            float gg = gsm[512 + b * 8 + jj];
            float go = gsm[768 + b * 8 + jj];
            float fi = 1.f / (1.f + expf(-gi));
            float ff = 1.f / (1.f + expf(-gf));
            float fo = 1.f / (1.f + expf(-go));
            float cn = ff * creg[r] + fi * tanhf(gg);
            float hv = fo * tanhf(cn);
            creg[r] = cn;
            int kp = j0 + (((jj & 3) << 1) | (jj >> 2));
            hout[b * NC_ + kp] = f2tf32(hv);
            hcat[((size_t)b * T_ + t) * NH_ + dir * NC_ + j0 + jj] = hv;
        }
        __syncthreads();   // all h writes done before arrival signal

        // prefetch next step's xp BEFORE the barrier (independent of h)
        if (s + 1 < T_) {
            int tn = dir ? (T_ - 2 - s) : (s + 1);
            size_t tb = (size_t)tn * H4_ + xcol;
            x0 = *(const float2*)(xp + ((size_t)(lr)      * T_) * H4_ + tb);
            x1 = *(const float2*)(xp + ((size_t)(lr + 8)  * T_) * H4_ + tb);
            x2 = *(const float2*)(xp + ((size_t)(lr + 16) * T_) * H4_ + tb);
            x3 = *(const float2*)(xp + ((size_t)(lr + 24) * T_) * H4_ + tb);
        }

        // per-direction grid barrier (sense-reversing, wrap-safe)
        if (tid == 0) {
            unsigned target = base + (unsigned)s + 1u;
            __threadfence();
            unsigned old = atomicAdd(barc, 1u);
            if (old == 63u) {
                atomicExch(barc, 0u);
                __threadfence();
                atomicExch(bars, target);
            } else {
                while ((int)(*(volatile unsigned*)bars - target) < 0) { }
                __threadfence();
            }
        }
        __syncthreads();
    }
}

// attention pool + classifier, one CTA per batch
__global__ __launch_bounds__(256) void attn_out(
    const float* __restrict__ H, const int* __restrict__ lens,
    const float* __restrict__ w_u, const float* __restrict__ b_u,
    const float* __restrict__ Wc, const float* __restrict__ bc,
    float* __restrict__ out)
{
    __shared__ float sc[T_];
    __shared__ float pooled[NH_];
    __shared__ float red[8];
    int b = blockIdx.x;
    int tid = threadIdx.x, lane = tid & 31, w = tid >> 5;
    int len = lens[b];
    const float* Hb = H + (size_t)b * T_ * NH_;

    for (int t = w; t < T_; t += 8) {
        const float* hp = Hb + (size_t)t * NH_;
        float s = 0.f;
        for (int d = lane; d < NH_; d += 32) s += hp[d] * w_u[d];
        s = warpSum(s);
        if (lane == 0) sc[t] = s + b_u[0];
    }
    __syncthreads();

    float m = -3.0e38f;
    for (int t = tid; t < len; t += 256) m = fmaxf(m, sc[t]);
    m = blockMax(m, red);

    float ps = 0.f;
    for (int t = tid; t < T_; t += 256) {
        float e = (t < len) ? expf(sc[t] - m) : 0.f;
        sc[t] = e; ps += e;
    }
    float S = blockSum(ps, red);
    float inv = 1.f / S;

    {
        float a0 = 0.f, a1 = 0.f, a2 = 0.f, a3 = 0.f;
        for (int t = 0; t < len; ++t) {
            float al = sc[t];
            const float* hp = Hb + (size_t)t * NH_ + tid;
            a0 += al * hp[0];
            a1 += al * hp[256];
            a2 += al * hp[512];
            a3 += al * hp[768];
        }
        pooled[tid]       = a0 * inv;
        pooled[tid + 256] = a1 * inv;
        pooled[tid + 512] = a2 * inv;
        pooled[tid + 768] = a3 * inv;
    }
    __syncthreads();

    {
        const float* wc = Wc + (size_t)w * NH_;
        float s = 0.f;
        for (int d = lane; d < NH_; d += 32) s += pooled[d] * wc[d];
        s = warpSum(s);
        if (lane == 0) out[b * NOUT_ + w] = s + bc[w];
    }
}

extern "C" void kernel_launch(void* const* d_in, const int* in_sizes, int n_in,
                              void* d_out, int out_size)
{
    const float* x    = (const float*)d_in[0];
    const int*   lens = (const int*)d_in[1];
    const float* W1   = (const float*)d_in[2];
    const float* b1   = (const float*)d_in[3];
    const float* g1   = (const float*)d_in[4];
    const float* be1  = (const float*)d_in[5];
    const float* W2   = (const float*)d_in[6];
    const float* b2   = (const float*)d_in[7];
    const float* g2   = (const float*)d_in[8];
    const float* be2  = (const float*)d_in[9];
    const float* wih  = (const float*)d_in[10];
    const float* whh  = (const float*)d_in[11];
    const float* bih  = (const float*)d_in[12];
    const float* bhh  = (const float*)d_in[13];
    const float* w_u  = (const float*)d_in[14];
    const float* b_u  = (const float*)d_in[15];
    const float* Wc   = (const float*)d_in[16];
    const float* bc   = (const float*)d_in[17];
    float* out = (float*)d_out;
    (void)in_sizes; (void)n_in; (void)out_size;

    float *bufA, *bufB, *bufC, *bufD;
    uint32_t *hA, *hB;
    cudaGetSymbolAddress((void**)&bufA, g_bufA);
    cudaGetSymbolAddress((void**)&bufB, g_bufB);
    cudaGetSymbolAddress((void**)&bufC, g_bufC);
    cudaGetSymbolAddress((void**)&bufD, g_bufD);
    cudaGetSymbolAddress((void**)&hA, g_hA);
    cudaGetSymbolAddress((void**)&hB, g_hB);

    cudaFuncSetAttribute(lstm_layer, cudaFuncAttributeMaxDynamicSharedMemorySize,
                         LSTM_SMEM);

    dim3 blk(256);
    dim3 gMLP(NH_ / 128, M_ / 128);
    dim3 gXP(H4_ / 128, M_ / 128);

    gemm_tf32<<<gMLP, blk>>>(x, W1, bufD, b1, nullptr, M_, NH_, FD_);
    ln_lrelu<<<M_, blk>>>(bufD, g1, be1, nullptr);
    gemm_tf32<<<gMLP, blk>>>(bufD, W2, bufC, b2, nullptr, M_, NH_, NH_);
    ln_lrelu<<<M_, blk>>>(bufC, g2, be2, lens);

    for (int layer = 0; layer < 2; ++layer) {
        const float* inbuf = (layer == 0) ? bufC : bufD;
        float* hcat = (layer == 0) ? bufD : bufC;
        size_t wo = (size_t)layer * 2 * H4_ * NH_;
        size_t ho = (size_t)layer * 2 * H4_ * NC_;
        size_t bo = (size_t)layer * 2 * H4_;

        gemm_tf32<<<gXP, blk>>>(inbuf, wih + wo, bufA,
                                bih + bo, bhh + bo, M_, H4_, NH_);
        gemm_tf32<<<gXP, blk>>>(inbuf, wih + wo + (size_t)H4_ * NH_, bufB,
                                bih + bo + H4_, bhh + bo + H4_, M_, H4_, NH_);

        lstm_layer<<<128, 128, LSTM_SMEM>>>(bufA, bufB, whh + ho, hA, hB, hcat);
    }

    attn_out<<<B_, blk>>>(bufC, lens, w_u, b_u, Wc, bc, out);
}

// round 11
// speedup vs baseline: 1.1898x; 1.1357x over previous
#include <cuda_runtime.h>
#include <math.h>
#include <stdint.h>

#define B_    32
#define T_    512
#define FD_   256
#define NH_   1024
#define NC_   512
#define H4_   2048
#define NOUT_ 8
#define M_    (B_ * T_)

__device__ float g_bufA[(size_t)M_ * H4_];
__device__ float g_bufB[(size_t)M_ * H4_];
__device__ float g_bufC[(size_t)M_ * NH_];
__device__ float g_bufD[(size_t)M_ * NH_];
__device__ uint32_t g_hA[2 * B_ * NC_];
__device__ uint32_t g_hB[2 * B_ * NC_];
__device__ unsigned g_bar_count;
__device__ unsigned g_bar_sense;

__device__ __forceinline__ float warpSum(float v) {
#pragma unroll
    for (int o = 16; o > 0; o >>= 1) v += __shfl_xor_sync(0xffffffffu, v, o);
    return v;
}
__device__ __forceinline__ float warpMax(float v) {
#pragma unroll
    for (int o = 16; o > 0; o >>= 1) v = fmaxf(v, __shfl_xor_sync(0xffffffffu, v, o));
    return v;
}
__device__ __forceinline__ float blockSum(float v, float* sh) {
    int lane = threadIdx.x & 31, w = threadIdx.x >> 5;
    v = warpSum(v);
    if (lane == 0) sh[w] = v;
    __syncthreads();
    if (w == 0) {
        float r = (lane < 8) ? sh[lane] : 0.f;
        r = warpSum(r);
        if (lane == 0) sh[0] = r;
    }
    __syncthreads();
    float r = sh[0];
    __syncthreads();
    return r;
}
__device__ __forceinline__ float blockMax(float v, float* sh) {
    int lane = threadIdx.x & 31, w = threadIdx.x >> 5;
    v = warpMax(v);
    if (lane == 0) sh[w] = v;
    __syncthreads();
    if (w == 0) {
        float r = (lane < 8) ? sh[lane] : -3.0e38f;
        r = warpMax(r);
        if (lane == 0) sh[0] = r;
    }
    __syncthreads();
    float r = sh[0];
    __syncthreads();
    return r;
}

__device__ __forceinline__ uint32_t f2tf32(float f) {
    uint32_t r;
    asm("cvt.rna.tf32.f32 %0, %1;" : "=r"(r) : "f"(f));
    return r;
}

__device__ __forceinline__ void mma_tf32(float* c, const uint32_t* a, const uint32_t* b) {
    asm volatile(
        "mma.sync.aligned.m16n8k8.row.col.f32.tf32.tf32.f32 "
        "{%0,%1,%2,%3}, {%4,%5,%6,%7}, {%8,%9}, {%0,%1,%2,%3};"
        : "+f"(c[0]), "+f"(c[1]), "+f"(c[2]), "+f"(c[3])
        : "r"(a[0]), "r"(a[1]), "r"(a[2]), "r"(a[3]), "r"(b[0]), "r"(b[1]));
}

// ---- tf32 tensor-core GEMM, cp.async double-buffered ----
// C[M,N] = A[M,K] @ W[N,K]^T + bias1 (+bias2). fp32 tiles in smem, cvt at frag load.
#define GA_(st, r, c) gsm_[((st) * 128 + (r)) * 36 + (c)]
#define GB_(st, r, c) gsm_[(2 * 128 * 36) + ((st) * 128 + (r)) * 36 + (c)]
#define GEMM_SMEM (4 * 128 * 36 * 4)

__global__ __launch_bounds__(256, 2) void gemm_tf32(
    const float* __restrict__ A, const float* __restrict__ W,
    float* __restrict__ C, const float* __restrict__ bias1,
    const float* __restrict__ bias2, int M, int N, int K)
{
    extern __shared__ float gsm_[];
    int tid = threadIdx.x;
    int lane = tid & 31, warp = tid >> 5;
    int wm = warp >> 2, wn = warp & 3;
    int lr = lane >> 2, lc = lane & 3;
    int bm = blockIdx.y * 128, bn = blockIdx.x * 128;
    int ldrow = tid >> 3;             // 0..31 (+32*i)
    int ldc4 = (tid & 7) << 2;

    float acc[4][4][4];
#pragma unroll
    for (int mt = 0; mt < 4; mt++)
#pragma unroll
        for (int nt = 0; nt < 4; nt++)
#pragma unroll
            for (int q = 0; q < 4; q++) acc[mt][nt][q] = 0.f;

    int niter = K >> 5;

    // prologue: stage 0
#pragma unroll
    for (int i = 0; i < 4; i++) {
        int row = ldrow + (i << 5);
        uint32_t da = (uint32_t)__cvta_generic_to_shared(&GA_(0, row, ldc4));
        asm volatile("cp.async.cg.shared.global [%0], [%1], 16;"
                     :: "r"(da), "l"(A + (size_t)(bm + row) * K + ldc4));
        uint32_t db = (uint32_t)__cvta_generic_to_shared(&GB_(0, row, ldc4));
        asm volatile("cp.async.cg.shared.global [%0], [%1], 16;"
                     :: "r"(db), "l"(W + (size_t)(bn + row) * K + ldc4));
    }
    asm volatile("cp.async.commit_group;");

    for (int it = 0; it < niter; ++it) {
        int cur = it & 1;
        if (it + 1 < niter) {
            int nxt = cur ^ 1;
            int k0 = (it + 1) << 5;
#pragma unroll
            for (int i = 0; i < 4; i++) {
                int row = ldrow + (i << 5);
                uint32_t da = (uint32_t)__cvta_generic_to_shared(&GA_(nxt, row, ldc4));
                asm volatile("cp.async.cg.shared.global [%0], [%1], 16;"
                             :: "r"(da), "l"(A + (size_t)(bm + row) * K + k0 + ldc4));
                uint32_t db = (uint32_t)__cvta_generic_to_shared(&GB_(nxt, row, ldc4));
                asm volatile("cp.async.cg.shared.global [%0], [%1], 16;"
                             :: "r"(db), "l"(W + (size_t)(bn + row) * K + k0 + ldc4));
            }
            asm volatile("cp.async.commit_group;");
            asm volatile("cp.async.wait_group 1;" ::: "memory");
        } else {
            asm volatile("cp.async.wait_group 0;" ::: "memory");
        }
        __syncthreads();

#pragma unroll
        for (int ks = 0; ks < 4; ks++) {
            int kc = ks << 3;
            uint32_t af[4][4], bf[4][2];
#pragma unroll
            for (int mt = 0; mt < 4; mt++) {
                int rb = wm * 64 + mt * 16;
                af[mt][0] = f2tf32(GA_(cur, rb + lr, kc + lc));
                af[mt][1] = f2tf32(GA_(cur, rb + lr + 8, kc + lc));
                af[mt][2] = f2tf32(GA_(cur, rb + lr, kc + lc + 4));
                af[mt][3] = f2tf32(GA_(cur, rb + lr + 8, kc + lc + 4));
            }
#pragma unroll
            for (int nt = 0; nt < 4; nt++) {
                int nb = wn * 32 + nt * 8;
                bf[nt][0] = f2tf32(GB_(cur, nb + lr, kc + lc));
                bf[nt][1] = f2tf32(GB_(cur, nb + lr, kc + lc + 4));
            }
#pragma unroll
            for (int mt = 0; mt < 4; mt++)
#pragma unroll
                for (int nt = 0; nt < 4; nt++)
                    mma_tf32(acc[mt][nt], af[mt], bf[nt]);
        }
        __syncthreads();
    }

#pragma unroll
    for (int nt = 0; nt < 4; nt++) {
        int col = bn + wn * 32 + nt * 8 + (lc << 1);
        float b0 = bias1 ? bias1[col] : 0.f;
        float b1 = bias1 ? bias1[col + 1] : 0.f;
        if (bias2) { b0 += bias2[col]; b1 += bias2[col + 1]; }
#pragma unroll
        for (int mt = 0; mt < 4; mt++) {
            int row = bm + wm * 64 + mt * 16 + lr;
            float2 v0 = make_float2(acc[mt][nt][0] + b0, acc[mt][nt][1] + b1);
            float2 v1 = make_float2(acc[mt][nt][2] + b0, acc[mt][nt][3] + b1);
            *(float2*)(C + (size_t)row * N + col) = v0;
            *(float2*)(C + (size_t)(row + 8) * N + col) = v1;
        }
    }
}

// LayerNorm + LeakyReLU (+ pad-mask zero) in place
__global__ __launch_bounds__(256) void ln_lrelu(
    float* __restrict__ X, const float* __restrict__ g,
    const float* __restrict__ be, const int* __restrict__ lens)
{
    __shared__ float sh[8];
    int row = blockIdx.x;
    float* x = X + (size_t)row * NH_;
    int tid = threadIdx.x;
    float v[4], s = 0.f, ss = 0.f;
#pragma unroll
    for (int i = 0; i < 4; i++) {
        float t = x[tid + (i << 8)];
        v[i] = t; s += t; ss += t * t;
    }
    float S = blockSum(s, sh);
    float SS = blockSum(ss, sh);
    float mean = S * (1.f / NH_);
    float inv = rsqrtf(SS * (1.f / NH_) - mean * mean + 1e-5f);
    bool z = false;
    if (lens) z = ((row & (T_ - 1)) >= lens[row >> 9]);
#pragma unroll
    for (int i = 0; i < 4; i++) {
        int c = tid + (i << 8);
        float y = (v[i] - mean) * inv * g[c] + be[c];
        y = (y >= 0.f) ? y : 0.01f * y;
        x[c] = z ? 0.f : y;
    }
}

// ---- persistent bidirectional LSTM layer, tensor-core recurrence (R8 exact) ----
#define LS_STRIDE 520
#define LS_H_OFF  (32 * LS_STRIDE)
#define LS_G_OFF  (64 * LS_STRIDE)
#define LSTM_SMEM ((64 * LS_STRIDE + 4 * 32 * 8) * 4)

__global__ __launch_bounds__(128) void lstm_layer(
    const float* __restrict__ xpf, const float* __restrict__ xpb,
    const float* __restrict__ whh,
    uint32_t* __restrict__ hA, uint32_t* __restrict__ hB,
    float* __restrict__ hcat)
{
    extern __shared__ float sm[];
    uint32_t* Wsm = (uint32_t*)sm;
    uint32_t* hsp = (uint32_t*)(sm + LS_H_OFF);
    float*    gsm = sm + LS_G_OFF;
    __shared__ unsigned sh_base;

    int dir = blockIdx.x >> 6;
    int j0 = (blockIdx.x & 63) << 3;
    const float* xp = dir ? xpb : xpf;
    const float* W = whh + (size_t)dir * H4_ * NC_;
    int tid = threadIdx.x;
    int w = tid >> 5, lane = tid & 31;
    int lr = lane >> 2, lc = lane & 3;

    for (int f = tid; f < 32 * 512; f += 128) {
        int n = f >> 9, k = f & 511;
        int g_ = n >> 3, jj = n & 7;
        float wv = W[(size_t)(g_ * NC_ + j0 + jj) * NC_ + k];
        int kp = (k & ~7) | ((k & 3) << 1) | ((k >> 2) & 1);
        Wsm[n * LS_STRIDE + kp] = f2tf32(wv);
    }
    if (tid == 0) sh_base = *(volatile unsigned*)&g_bar_sense;
    __syncthreads();
    unsigned base = sh_base;

    float creg[2] = {0.f, 0.f};

    const uint32_t* hr0 = hsp + lr * LS_STRIDE + 2 * lc;
    const uint32_t* wb  = Wsm + (w * 8 + lr) * LS_STRIDE + 2 * lc;
    size_t xcol = (size_t)w * NC_ + j0 + 2 * lc;

    for (int s = 0; s < T_; ++s) {
        int t = dir ? (T_ - 1 - s) : s;
        float2 x0, x1, x2, x3;
        {
            size_t tb = (size_t)t * H4_ + xcol;
            x0 = *(const float2*)(xp + ((size_t)(lr)      * T_) * H4_ + tb);
            x1 = *(const float2*)(xp + ((size_t)(lr + 8)  * T_) * H4_ + tb);
            x2 = *(const float2*)(xp + ((size_t)(lr + 16) * T_) * H4_ + tb);
            x3 = *(const float2*)(xp + ((size_t)(lr + 24) * T_) * H4_ + tb);
        }
        float a0a[4] = {0,0,0,0}, a0b[4] = {0,0,0,0};
        float a1a[4] = {0,0,0,0}, a1b[4] = {0,0,0,0};
        if (s > 0) {
            const uint32_t* hin = ((s & 1) ? hB : hA) + dir * B_ * NC_;
#pragma unroll
            for (int i = 0; i < 32; i++) {
                uint4 v = *(const uint4*)(hin + i * NC_ + tid * 4);
                *(uint4*)(hsp + i * LS_STRIDE + tid * 4) = v;
            }
            __syncthreads();
#pragma unroll 4
            for (int kc = 0; kc < 512; kc += 16) {
                uint2 p0 = *(const uint2*)(hr0 + kc);
                uint2 p1 = *(const uint2*)(hr0 + 8 * LS_STRIDE + kc);
                uint2 p2 = *(const uint2*)(hr0 + 16 * LS_STRIDE + kc);
                uint2 p3 = *(const uint2*)(hr0 + 24 * LS_STRIDE + kc);
                uint2 bv = *(const uint2*)(wb + kc);
                uint32_t A0[4] = {p0.x, p1.x, p0.y, p1.y};
                uint32_t A1[4] = {p2.x, p3.x, p2.y, p3.y};
                uint32_t Bf[2] = {bv.x, bv.y};
                mma_tf32(a0a, A0, Bf);
                mma_tf32(a1a, A1, Bf);
                uint2 q0 = *(const uint2*)(hr0 + kc + 8);
                uint2 q1 = *(const uint2*)(hr0 + 8 * LS_STRIDE + kc + 8);
                uint2 q2 = *(const uint2*)(hr0 + 16 * LS_STRIDE + kc + 8);
                uint2 q3 = *(const uint2*)(hr0 + 24 * LS_STRIDE + kc + 8);
                uint2 bw = *(const uint2*)(wb + kc + 8);
                uint32_t A0b[4] = {q0.x, q1.x, q0.y, q1.y};
                uint32_t A1b[4] = {q2.x, q3.x, q2.y, q3.y};
                uint32_t Bg[2] = {bw.x, bw.y};
                mma_tf32(a0b, A0b, Bg);
                mma_tf32(a1b, A1b, Bg);
            }
        }
        {
            float* gw = gsm + w * 256;
            *(float2*)(gw + lr * 8 + 2 * lc) =
                make_float2(a0a[0] + a0b[0] + x0.x, a0a[1] + a0b[1] + x0.y);
            *(float2*)(gw + (lr + 8) * 8 + 2 * lc) =
                make_float2(a0a[2] + a0b[2] + x1.x, a0a[3] + a0b[3] + x1.y);
            *(float2*)(gw + (lr + 16) * 8 + 2 * lc) =
                make_float2(a1a[0] + a1b[0] + x2.x, a1a[1] + a1b[1] + x2.y);
            *(float2*)(gw + (lr + 24) * 8 + 2 * lc) =
                make_float2(a1a[2] + a1b[2] + x3.x, a1a[3] + a1b[3] + x3.y);
        }
        __syncthreads();

        uint32_t* hout = ((s & 1) ? hA : hB) + dir * B_ * NC_;
#pragma unroll
        for (int r = 0; r < 2; r++) {
            int e = tid + (r << 7);
            int b = e >> 3, jj = e & 7;
            float gi = gsm[b * 8 + jj];
            float gf = gsm[256 + b * 8 + jj];
            float gg = gsm[512 + b * 8 + jj];
            float go = gsm[768 + b * 8 + jj];
            float fi = 1.f / (1.f + expf(-gi));
            float ff = 1.f / (1.f + expf(-gf));
            float fo = 1.f / (1.f + expf(-go));
            float cn = ff * creg[r] + fi * tanhf(gg);
            float hv = fo * tanhf(cn);
            creg[r] = cn;
            int kp = j0 + (((jj & 3) << 1) | (jj >> 2));
            hout[b * NC_ + kp] = f2tf32(hv);
            hcat[((size_t)b * T_ + t) * NH_ + dir * NC_ + j0 + jj] = hv;
        }
        __syncthreads();

        if (tid == 0) {
            unsigned target = base + (unsigned)s + 1u;
            __threadfence();
            unsigned old = atomicAdd(&g_bar_count, 1u);
            if (old == 127u) {
                atomicExch(&g_bar_count, 0u);
                __threadfence();
                atomicExch(&g_bar_sense, target);
            } else {
                while ((int)(*(volatile unsigned*)&g_bar_sense - target) < 0) { }
                __threadfence();
            }
        }
        __syncthreads();
    }
}

// attention pool + classifier, one CTA per batch
__global__ __launch_bounds__(256) void attn_out(
    const float* __restrict__ H, const int* __restrict__ lens,
    const float* __restrict__ w_u, const float* __restrict__ b_u,
    const float* __restrict__ Wc, const float* __restrict__ bc,
    float* __restrict__ out)
{
    __shared__ float sc[T_];
    __shared__ float pooled[NH_];
    __shared__ float red[8];
    int b = blockIdx.x;
    int tid = threadIdx.x, lane = tid & 31, w = tid >> 5;
    int len = lens[b];
    const float* Hb = H + (size_t)b * T_ * NH_;

    for (int t = w; t < T_; t += 8) {
        const float* hp = Hb + (size_t)t * NH_;
        float s = 0.f;
        for (int d = lane; d < NH_; d += 32) s += hp[d] * w_u[d];
        s = warpSum(s);
        if (lane == 0) sc[t] = s + b_u[0];
    }
    __syncthreads();

    float m = -3.0e38f;
    for (int t = tid; t < len; t += 256) m = fmaxf(m, sc[t]);
    m = blockMax(m, red);

    float ps = 0.f;
    for (int t = tid; t < T_; t += 256) {
        float e = (t < len) ? expf(sc[t] - m) : 0.f;
        sc[t] = e; ps += e;
    }
    float S = blockSum(ps, red);
    float inv = 1.f / S;

    {
        float a0 = 0.f, a1 = 0.f, a2 = 0.f, a3 = 0.f;
        for (int t = 0; t < len; ++t) {
            float al = sc[t];
            const float* hp = Hb + (size_t)t * NH_ + tid;
            a0 += al * hp[0];
            a1 += al * hp[256];
            a2 += al * hp[512];
            a3 += al * hp[768];
        }
        pooled[tid]       = a0 * inv;
        pooled[tid + 256] = a1 * inv;
        pooled[tid + 512] = a2 * inv;
        pooled[tid + 768] = a3 * inv;
    }
    __syncthreads();

    {
        const float* wc = Wc + (size_t)w * NH_;
        float s = 0.f;
        for (int d = lane; d < NH_; d += 32) s += pooled[d] * wc[d];
        s = warpSum(s);
        if (lane == 0) out[b * NOUT_ + w] = s + bc[w];
    }
}

extern "C" void kernel_launch(void* const* d_in, const int* in_sizes, int n_in,
                              void* d_out, int out_size)
{
    const float* x    = (const float*)d_in[0];
    const int*   lens = (const int*)d_in[1];
    const float* W1   = (const float*)d_in[2];
    const float* b1   = (const float*)d_in[3];
    const float* g1   = (const float*)d_in[4];
    const float* be1  = (const float*)d_in[5];
    const float* W2   = (const float*)d_in[6];
    const float* b2   = (const float*)d_in[7];
    const float* g2   = (const float*)d_in[8];
    const float* be2  = (const float*)d_in[9];
    const float* wih  = (const float*)d_in[10];
    const float* whh  = (const float*)d_in[11];
    const float* bih  = (const float*)d_in[12];
    const float* bhh  = (const float*)d_in[13];
    const float* w_u  = (const float*)d_in[14];
    const float* b_u  = (const float*)d_in[15];
    const float* Wc   = (const float*)d_in[16];
    const float* bc   = (const float*)d_in[17];
    float* out = (float*)d_out;
    (void)in_sizes; (void)n_in; (void)out_size;

    float *bufA, *bufB, *bufC, *bufD;
    uint32_t *hA, *hB;
    cudaGetSymbolAddress((void**)&bufA, g_bufA);
    cudaGetSymbolAddress((void**)&bufB, g_bufB);
    cudaGetSymbolAddress((void**)&bufC, g_bufC);
    cudaGetSymbolAddress((void**)&bufD, g_bufD);
    cudaGetSymbolAddress((void**)&hA, g_hA);
    cudaGetSymbolAddress((void**)&hB, g_hB);

    cudaFuncSetAttribute(lstm_layer, cudaFuncAttributeMaxDynamicSharedMemorySize,
                         LSTM_SMEM);
    cudaFuncSetAttribute(gemm_tf32, cudaFuncAttributeMaxDynamicSharedMemorySize,
                         GEMM_SMEM);

    dim3 blk(256);
    dim3 gMLP(NH_ / 128, M_ / 128);
    dim3 gXP(H4_ / 128, M_ / 128);

    gemm_tf32<<<gMLP, blk, GEMM_SMEM>>>(x, W1, bufD, b1, nullptr, M_, NH_, FD_);
    ln_lrelu<<<M_, blk>>>(bufD, g1, be1, nullptr);
    gemm_tf32<<<gMLP, blk, GEMM_SMEM>>>(bufD, W2, bufC, b2, nullptr, M_, NH_, NH_);
    ln_lrelu<<<M_, blk>>>(bufC, g2, be2, lens);

    for (int layer = 0; layer < 2; ++layer) {
        const float* inbuf = (layer == 0) ? bufC : bufD;
        float* hcat = (layer == 0) ? bufD : bufC;
        size_t wo = (size_t)layer * 2 * H4_ * NH_;
        size_t ho = (size_t)layer * 2 * H4_ * NC_;
        size_t bo = (size_t)layer * 2 * H4_;

        gemm_tf32<<<gXP, blk, GEMM_SMEM>>>(inbuf, wih + wo, bufA,
                                           bih + bo, bhh + bo, M_, H4_, NH_);
        gemm_tf32<<<gXP, blk, GEMM_SMEM>>>(inbuf, wih + wo + (size_t)H4_ * NH_, bufB,
                                           bih + bo + H4_, bhh + bo + H4_, M_, H4_, NH_);

        lstm_layer<<<128, 128, LSTM_SMEM>>>(bufA, bufB, whh + ho, hA, hB, hcat);
    }

    attn_out<<<B_, blk>>>(bufC, lens, w_u, b_u, Wc, bc, out);
}

// round 12
// speedup vs baseline: 1.5231x; 1.2802x over previous
#include <cuda_runtime.h>
#include <math.h>
#include <stdint.h>

#define B_    32
#define T_    512
#define FD_   256
#define NH_   1024
#define NC_   512
#define H4_   2048
#define NOUT_ 8
#define M_    (B_ * T_)

__device__ float g_bufA[(size_t)M_ * H4_];
__device__ float g_bufB[(size_t)M_ * H4_];
__device__ float g_bufC[(size_t)M_ * NH_];
__device__ float g_bufD[(size_t)M_ * NH_];
__device__ uint32_t g_hA[2 * B_ * NC_];
__device__ uint32_t g_hB[2 * B_ * NC_];
__device__ unsigned g_bar_count;
__device__ unsigned g_bar_sense;

__device__ __forceinline__ float warpSum(float v) {
#pragma unroll
    for (int o = 16; o > 0; o >>= 1) v += __shfl_xor_sync(0xffffffffu, v, o);
    return v;
}
__device__ __forceinline__ float warpMax(float v) {
#pragma unroll
    for (int o = 16; o > 0; o >>= 1) v = fmaxf(v, __shfl_xor_sync(0xffffffffu, v, o));
    return v;
}
__device__ __forceinline__ float blockSum(float v, float* sh) {
    int lane = threadIdx.x & 31, w = threadIdx.x >> 5;
    v = warpSum(v);
    if (lane == 0) sh[w] = v;
    __syncthreads();
    if (w == 0) {
        float r = (lane < 8) ? sh[lane] : 0.f;
        r = warpSum(r);
        if (lane == 0) sh[0] = r;
    }
    __syncthreads();
    float r = sh[0];
    __syncthreads();
    return r;
}
__device__ __forceinline__ float blockMax(float v, float* sh) {
    int lane = threadIdx.x & 31, w = threadIdx.x >> 5;
    v = warpMax(v);
    if (lane == 0) sh[w] = v;
    __syncthreads();
    if (w == 0) {
        float r = (lane < 8) ? sh[lane] : -3.0e38f;
        r = warpMax(r);
        if (lane == 0) sh[0] = r;
    }
    __syncthreads();
    float r = sh[0];
    __syncthreads();
    return r;
}

__device__ __forceinline__ uint32_t f2tf32(float f) {
    uint32_t r;
    asm("cvt.rna.tf32.f32 %0, %1;" : "=r"(r) : "f"(f));
    return r;
}

__device__ __forceinline__ void mma_tf32(float* c, const uint32_t* a, const uint32_t* b) {
    asm volatile(
        "mma.sync.aligned.m16n8k8.row.col.f32.tf32.tf32.f32 "
        "{%0,%1,%2,%3}, {%4,%5,%6,%7}, {%8,%9}, {%0,%1,%2,%3};"
        : "+f"(c[0]), "+f"(c[1]), "+f"(c[2]), "+f"(c[3])
        : "r"(a[0]), "r"(a[1]), "r"(a[2]), "r"(a[3]), "r"(b[0]), "r"(b[1]));
}

// ---- tf32 tensor-core GEMM, cp.async double-buffered (R11) ----
#define GA_(st, r, c) gsm_[((st) * 128 + (r)) * 36 + (c)]
#define GB_(st, r, c) gsm_[(2 * 128 * 36) + ((st) * 128 + (r)) * 36 + (c)]
#define GEMM_SMEM (4 * 128 * 36 * 4)

__global__ __launch_bounds__(256, 2) void gemm_tf32(
    const float* __restrict__ A, const float* __restrict__ W,
    float* __restrict__ C, const float* __restrict__ bias1,
    const float* __restrict__ bias2, int M, int N, int K)
{
    extern __shared__ float gsm_[];
    int tid = threadIdx.x;
    int lane = tid & 31, warp = tid >> 5;
    int wm = warp >> 2, wn = warp & 3;
    int lr = lane >> 2, lc = lane & 3;
    int bm = blockIdx.y * 128, bn = blockIdx.x * 128;
    int ldrow = tid >> 3;
    int ldc4 = (tid & 7) << 2;

    float acc[4][4][4];
#pragma unroll
    for (int mt = 0; mt < 4; mt++)
#pragma unroll
        for (int nt = 0; nt < 4; nt++)
#pragma unroll
            for (int q = 0; q < 4; q++) acc[mt][nt][q] = 0.f;

    int niter = K >> 5;

#pragma unroll
    for (int i = 0; i < 4; i++) {
        int row = ldrow + (i << 5);
        uint32_t da = (uint32_t)__cvta_generic_to_shared(&GA_(0, row, ldc4));
        asm volatile("cp.async.cg.shared.global [%0], [%1], 16;"
                     :: "r"(da), "l"(A + (size_t)(bm + row) * K + ldc4));
        uint32_t db = (uint32_t)__cvta_generic_to_shared(&GB_(0, row, ldc4));
        asm volatile("cp.async.cg.shared.global [%0], [%1], 16;"
                     :: "r"(db), "l"(W + (size_t)(bn + row) * K + ldc4));
    }
    asm volatile("cp.async.commit_group;");

    for (int it = 0; it < niter; ++it) {
        int cur = it & 1;
        if (it + 1 < niter) {
            int nxt = cur ^ 1;
            int k0 = (it + 1) << 5;
#pragma unroll
            for (int i = 0; i < 4; i++) {
                int row = ldrow + (i << 5);
                uint32_t da = (uint32_t)__cvta_generic_to_shared(&GA_(nxt, row, ldc4));
                asm volatile("cp.async.cg.shared.global [%0], [%1], 16;"
                             :: "r"(da), "l"(A + (size_t)(bm + row) * K + k0 + ldc4));
                uint32_t db = (uint32_t)__cvta_generic_to_shared(&GB_(nxt, row, ldc4));
                asm volatile("cp.async.cg.shared.global [%0], [%1], 16;"
                             :: "r"(db), "l"(W + (size_t)(bn + row) * K + k0 + ldc4));
            }
            asm volatile("cp.async.commit_group;");
            asm volatile("cp.async.wait_group 1;" ::: "memory");
        } else {
            asm volatile("cp.async.wait_group 0;" ::: "memory");
        }
        __syncthreads();

#pragma unroll
        for (int ks = 0; ks < 4; ks++) {
            int kc = ks << 3;
            uint32_t af[4][4], bf[4][2];
#pragma unroll
            for (int mt = 0; mt < 4; mt++) {
                int rb = wm * 64 + mt * 16;
                af[mt][0] = f2tf32(GA_(cur, rb + lr, kc + lc));
                af[mt][1] = f2tf32(GA_(cur, rb + lr + 8, kc + lc));
                af[mt][2] = f2tf32(GA_(cur, rb + lr, kc + lc + 4));
                af[mt][3] = f2tf32(GA_(cur, rb + lr + 8, kc + lc + 4));
            }
#pragma unroll
            for (int nt = 0; nt < 4; nt++) {
                int nb = wn * 32 + nt * 8;
                bf[nt][0] = f2tf32(GB_(cur, nb + lr, kc + lc));
                bf[nt][1] = f2tf32(GB_(cur, nb + lr, kc + lc + 4));
            }
#pragma unroll
            for (int mt = 0; mt < 4; mt++)
#pragma unroll
                for (int nt = 0; nt < 4; nt++)
                    mma_tf32(acc[mt][nt], af[mt], bf[nt]);
        }
        __syncthreads();
    }

#pragma unroll
    for (int nt = 0; nt < 4; nt++) {
        int col = bn + wn * 32 + nt * 8 + (lc << 1);
        float b0 = bias1 ? bias1[col] : 0.f;
        float b1 = bias1 ? bias1[col + 1] : 0.f;
        if (bias2) { b0 += bias2[col]; b1 += bias2[col + 1]; }
#pragma unroll
        for (int mt = 0; mt < 4; mt++) {
            int row = bm + wm * 64 + mt * 16 + lr;
            float2 v0 = make_float2(acc[mt][nt][0] + b0, acc[mt][nt][1] + b1);
            float2 v1 = make_float2(acc[mt][nt][2] + b0, acc[mt][nt][3] + b1);
            *(float2*)(C + (size_t)row * N + col) = v0;
            *(float2*)(C + (size_t)(row + 8) * N + col) = v1;
        }
    }
}

// LayerNorm + LeakyReLU (+ pad-mask zero) in place
__global__ __launch_bounds__(256) void ln_lrelu(
    float* __restrict__ X, const float* __restrict__ g,
    const float* __restrict__ be, const int* __restrict__ lens)
{
    __shared__ float sh[8];
    int row = blockIdx.x;
    float* x = X + (size_t)row * NH_;
    int tid = threadIdx.x;
    float v[4], s = 0.f, ss = 0.f;
#pragma unroll
    for (int i = 0; i < 4; i++) {
        float t = x[tid + (i << 8)];
        v[i] = t; s += t; ss += t * t;
    }
    float S = blockSum(s, sh);
    float SS = blockSum(ss, sh);
    float mean = S * (1.f / NH_);
    float inv = rsqrtf(SS * (1.f / NH_) - mean * mean + 1e-5f);
    bool z = false;
    if (lens) z = ((row & (T_ - 1)) >= lens[row >> 9]);
#pragma unroll
    for (int i = 0; i < 4; i++) {
        int c = tid + (i << 8);
        float y = (v[i] - mean) * inv * g[c] + be[c];
        y = (y >= 0.f) ? y : 0.01f * y;
        x[c] = z ? 0.f : y;
    }
}

// ---- persistent bidirectional LSTM layer, tensor-core, 256 threads, K-split ----
// 128 CTAs = 2 dirs x 64 chunks. 8 warps = 2 K-groups x 4 gates.
// Group p accumulates k in [p*256, p*256+256); partials summed in cell phase.
#define LS_STRIDE 520
#define LS_H_OFF  (32 * LS_STRIDE)
#define LS_G_OFF  (64 * LS_STRIDE)
#define LSTM_SMEM ((64 * LS_STRIDE + 2048) * 4)

__global__ __launch_bounds__(256) void lstm_layer(
    const float* __restrict__ xpf, const float* __restrict__ xpb,
    const float* __restrict__ whh,
    uint32_t* __restrict__ hA, uint32_t* __restrict__ hB,
    float* __restrict__ hcat)
{
    extern __shared__ float sm[];
    uint32_t* Wsm = (uint32_t*)sm;                  // [32 n][520] tf32, k-permuted
    uint32_t* hsp = (uint32_t*)(sm + LS_H_OFF);     // [32 b][520] tf32, k-permuted
    float*    gsm = sm + LS_G_OFF;                  // [2 part][4 gate][32 b][8 jj]
    __shared__ unsigned sh_base;

    int dir = blockIdx.x >> 6;
    int j0 = (blockIdx.x & 63) << 3;
    const float* xp = dir ? xpb : xpf;
    const float* W = whh + (size_t)dir * H4_ * NC_;
    int tid = threadIdx.x;
    int w = tid >> 5, lane = tid & 31;
    int g = w & 3, part = w >> 2;
    int koff = part << 8;                 // 0 or 256
    int lr = lane >> 2, lc = lane & 3;

    // cache + convert + permute whh slice (32 gate-cols x 512 k)
    for (int f = tid; f < 32 * 512; f += 256) {
        int n = f >> 9, k = f & 511;
        int g_ = n >> 3, jj = n & 7;
        float wv = W[(size_t)(g_ * NC_ + j0 + jj) * NC_ + k];
        int kp = (k & ~7) | ((k & 3) << 1) | ((k >> 2) & 1);
        Wsm[n * LS_STRIDE + kp] = f2tf32(wv);
    }
    if (tid == 0) sh_base = *(volatile unsigned*)&g_bar_sense;
    __syncthreads();
    unsigned base = sh_base;

    float creg = 0.f;
    int eb = tid >> 3, ej = tid & 7;      // cell element: batch, jj

    const uint32_t* hr0 = hsp + lr * LS_STRIDE + koff + 2 * lc;
    const uint32_t* wb  = Wsm + (g * 8 + lr) * LS_STRIDE + koff + 2 * lc;
    size_t xcol = (size_t)g * NC_ + j0 + 2 * lc;

    for (int s = 0; s < T_; ++s) {
        int t = dir ? (T_ - 1 - s) : s;
        // xp prefetch (group 0 only; carries GEMM bias)
        float2 x0, x1, x2, x3;
        if (part == 0) {
            size_t tb = (size_t)t * H4_ + xcol;
            x0 = *(const float2*)(xp + ((size_t)(lr)      * T_) * H4_ + tb);
            x1 = *(const float2*)(xp + ((size_t)(lr + 8)  * T_) * H4_ + tb);
            x2 = *(const float2*)(xp + ((size_t)(lr + 16) * T_) * H4_ + tb);
            x3 = *(const float2*)(xp + ((size_t)(lr + 24) * T_) * H4_ + tb);
        } else {
            x0 = x1 = x2 = x3 = make_float2(0.f, 0.f);
        }
        float a0a[4] = {0,0,0,0}, a0b[4] = {0,0,0,0};
        float a1a[4] = {0,0,0,0}, a1b[4] = {0,0,0,0};
        if (s > 0) {
            const uint32_t* hin = ((s & 1) ? hB : hA) + dir * B_ * NC_;
            // stage full h tile (tf32 + permuted): 4096 uint4 over 256 threads
#pragma unroll
            for (int i = 0; i < 16; i++) {
                int idx = tid + (i << 8);
                int row = idx >> 7;
                int c4 = (idx & 127) << 2;
                uint4 v = *(const uint4*)(hin + row * NC_ + c4);
                *(uint4*)(hsp + row * LS_STRIDE + c4) = v;
            }
            __syncthreads();
#pragma unroll 4
            for (int kc = 0; kc < 256; kc += 16) {
                uint2 p0 = *(const uint2*)(hr0 + kc);
                uint2 p1 = *(const uint2*)(hr0 + 8 * LS_STRIDE + kc);
                uint2 p2 = *(const uint2*)(hr0 + 16 * LS_STRIDE + kc);
                uint2 p3 = *(const uint2*)(hr0 + 24 * LS_STRIDE + kc);
                uint2 bv = *(const uint2*)(wb + kc);
                uint32_t A0[4] = {p0.x, p1.x, p0.y, p1.y};
                uint32_t A1[4] = {p2.x, p3.x, p2.y, p3.y};
                uint32_t Bf[2] = {bv.x, bv.y};
                mma_tf32(a0a, A0, Bf);
                mma_tf32(a1a, A1, Bf);
                uint2 q0 = *(const uint2*)(hr0 + kc + 8);
                uint2 q1 = *(const uint2*)(hr0 + 8 * LS_STRIDE + kc + 8);
                uint2 q2 = *(const uint2*)(hr0 + 16 * LS_STRIDE + kc + 8);
                uint2 q3 = *(const uint2*)(hr0 + 24 * LS_STRIDE + kc + 8);
                uint2 bw = *(const uint2*)(wb + kc + 8);
                uint32_t A0b[4] = {q0.x, q1.x, q0.y, q1.y};
                uint32_t A1b[4] = {q2.x, q3.x, q2.y, q3.y};
                uint32_t Bg[2] = {bw.x, bw.y};
                mma_tf32(a0b, A0b, Bg);
                mma_tf32(a1b, A1b, Bg);
            }
        }
        // write this group's partial gates (+ xp for group 0)
        {
            float* gw = gsm + part * 1024 + g * 256;
            *(float2*)(gw + lr * 8 + 2 * lc) =
                make_float2(a0a[0] + a0b[0] + x0.x, a0a[1] + a0b[1] + x0.y);
            *(float2*)(gw + (lr + 8) * 8 + 2 * lc) =
                make_float2(a0a[2] + a0b[2] + x1.x, a0a[3] + a0b[3] + x1.y);
            *(float2*)(gw + (lr + 16) * 8 + 2 * lc) =
                make_float2(a1a[0] + a1b[0] + x2.x, a1a[1] + a1b[1] + x2.y);
            *(float2*)(gw + (lr + 24) * 8 + 2 * lc) =
                make_float2(a1a[2] + a1b[2] + x3.x, a1a[3] + a1b[3] + x3.y);
        }
        __syncthreads();

        // cell update: one element per thread, sum the two K-partials
        uint32_t* hout = ((s & 1) ? hA : hB) + dir * B_ * NC_;
        {
            int e = eb * 8 + ej;
            float gi = gsm[e]       + gsm[1024 + e];
            float gf = gsm[256 + e] + gsm[1280 + e];
            float gg = gsm[512 + e] + gsm[1536 + e];
            float go = gsm[768 + e] + gsm[1792 + e];
            float fi = 1.f / (1.f + expf(-gi));
            float ff = 1.f / (1.f + expf(-gf));
            float fo = 1.f / (1.f + expf(-go));
            float cn = ff * creg + fi * tanhf(gg);
            float hv = fo * tanhf(cn);
            creg = cn;
            int kp = j0 + (((ej & 3) << 1) | (ej >> 2));
            hout[eb * NC_ + kp] = f2tf32(hv);
            hcat[((size_t)eb * T_ + t) * NH_ + dir * NC_ + j0 + ej] = hv;
        }
        __syncthreads();   // all h writes done before arrival signal

        // grid-wide barrier (sense-reversing, wrap-safe)
        if (tid == 0) {
            unsigned target = base + (unsigned)s + 1u;
            __threadfence();
            unsigned old = atomicAdd(&g_bar_count, 1u);
            if (old == 127u) {
                atomicExch(&g_bar_count, 0u);
                __threadfence();
                atomicExch(&g_bar_sense, target);
            } else {
                while ((int)(*(volatile unsigned*)&g_bar_sense - target) < 0) { }
                __threadfence();
            }
        }
        __syncthreads();
    }
}

// attention pool + classifier, one CTA per batch
__global__ __launch_bounds__(256) void attn_out(
    const float* __restrict__ H, const int* __restrict__ lens,
    const float* __restrict__ w_u, const float* __restrict__ b_u,
    const float* __restrict__ Wc, const float* __restrict__ bc,
    float* __restrict__ out)
{
    __shared__ float sc[T_];
    __shared__ float pooled[NH_];
    __shared__ float red[8];
    int b = blockIdx.x;
    int tid = threadIdx.x, lane = tid & 31, w = tid >> 5;
    int len = lens[b];
    const float* Hb = H + (size_t)b * T_ * NH_;

    for (int t = w; t < T_; t += 8) {
        const float* hp = Hb + (size_t)t * NH_;
        float s = 0.f;
        for (int d = lane; d < NH_; d += 32) s += hp[d] * w_u[d];
        s = warpSum(s);
        if (lane == 0) sc[t] = s + b_u[0];
    }
    __syncthreads();

    float m = -3.0e38f;
    for (int t = tid; t < len; t += 256) m = fmaxf(m, sc[t]);
    m = blockMax(m, red);

    float ps = 0.f;
    for (int t = tid; t < T_; t += 256) {
        float e = (t < len) ? expf(sc[t] - m) : 0.f;
        sc[t] = e; ps += e;
    }
    float S = blockSum(ps, red);
    float inv = 1.f / S;

    {
        float a0 = 0.f, a1 = 0.f, a2 = 0.f, a3 = 0.f;
        for (int t = 0; t < len; ++t) {
            float al = sc[t];
            const float* hp = Hb + (size_t)t * NH_ + tid;
            a0 += al * hp[0];
            a1 += al * hp[256];
            a2 += al * hp[512];
            a3 += al * hp[768];
        }
        pooled[tid]       = a0 * inv;
        pooled[tid + 256] = a1 * inv;
        pooled[tid + 512] = a2 * inv;
        pooled[tid + 768] = a3 * inv;
    }
    __syncthreads();

    {
        const float* wc = Wc + (size_t)w * NH_;
        float s = 0.f;
        for (int d = lane; d < NH_; d += 32) s += pooled[d] * wc[d];
        s = warpSum(s);
        if (lane == 0) out[b * NOUT_ + w] = s + bc[w];
    }
}

extern "C" void kernel_launch(void* const* d_in, const int* in_sizes, int n_in,
                              void* d_out, int out_size)
{
    const float* x    = (const float*)d_in[0];
    const int*   lens = (const int*)d_in[1];
    const float* W1   = (const float*)d_in[2];
    const float* b1   = (const float*)d_in[3];
    const float* g1   = (const float*)d_in[4];
    const float* be1  = (const float*)d_in[5];
    const float* W2   = (const float*)d_in[6];
    const float* b2   = (const float*)d_in[7];
    const float* g2   = (const float*)d_in[8];
    const float* be2  = (const float*)d_in[9];
    const float* wih  = (const float*)d_in[10];
    const float* whh  = (const float*)d_in[11];
    const float* bih  = (const float*)d_in[12];
    const float* bhh  = (const float*)d_in[13];
    const float* w_u  = (const float*)d_in[14];
    const float* b_u  = (const float*)d_in[15];
    const float* Wc   = (const float*)d_in[16];
    const float* bc   = (const float*)d_in[17];
    float* out = (float*)d_out;
    (void)in_sizes; (void)n_in; (void)out_size;

    float *bufA, *bufB, *bufC, *bufD;
    uint32_t *hA, *hB;
    cudaGetSymbolAddress((void**)&bufA, g_bufA);
    cudaGetSymbolAddress((void**)&bufB, g_bufB);
    cudaGetSymbolAddress((void**)&bufC, g_bufC);
    cudaGetSymbolAddress((void**)&bufD, g_bufD);
    cudaGetSymbolAddress((void**)&hA, g_hA);
    cudaGetSymbolAddress((void**)&hB, g_hB);

    cudaFuncSetAttribute(lstm_layer, cudaFuncAttributeMaxDynamicSharedMemorySize,
                         LSTM_SMEM);
    cudaFuncSetAttribute(gemm_tf32, cudaFuncAttributeMaxDynamicSharedMemorySize,
                         GEMM_SMEM);

    dim3 blk(256);
    dim3 gMLP(NH_ / 128, M_ / 128);
    dim3 gXP(H4_ / 128, M_ / 128);

    gemm_tf32<<<gMLP, blk, GEMM_SMEM>>>(x, W1, bufD, b1, nullptr, M_, NH_, FD_);
    ln_lrelu<<<M_, blk>>>(bufD, g1, be1, nullptr);
    gemm_tf32<<<gMLP, blk, GEMM_SMEM>>>(bufD, W2, bufC, b2, nullptr, M_, NH_, NH_);
    ln_lrelu<<<M_, blk>>>(bufC, g2, be2, lens);

    for (int layer = 0; layer < 2; ++layer) {
        const float* inbuf = (layer == 0) ? bufC : bufD;
        float* hcat = (layer == 0) ? bufD : bufC;
        size_t wo = (size_t)layer * 2 * H4_ * NH_;
        size_t ho = (size_t)layer * 2 * H4_ * NC_;
        size_t bo = (size_t)layer * 2 * H4_;

        gemm_tf32<<<gXP, blk, GEMM_SMEM>>>(inbuf, wih + wo, bufA,
                                           bih + bo, bhh + bo, M_, H4_, NH_);
        gemm_tf32<<<gXP, blk, GEMM_SMEM>>>(inbuf, wih + wo + (size_t)H4_ * NH_, bufB,
                                           bih + bo + H4_, bhh + bo + H4_, M_, H4_, NH_);

        lstm_layer<<<128, 256, LSTM_SMEM>>>(bufA, bufB, whh + ho, hA, hB, hcat);
    }

    attn_out<<<B_, blk>>>(bufC, lens, w_u, b_u, Wc, bc, out);
}

// round 13
// speedup vs baseline: 1.5757x; 1.0345x over previous
#include <cuda_runtime.h>
#include <math.h>
#include <stdint.h>

#define B_    32
#define T_    512
#define FD_   256
#define NH_   1024
#define NC_   512
#define H4_   2048
#define NOUT_ 8
#define M_    (B_ * T_)

__device__ float g_bufA[(size_t)M_ * H4_];
__device__ float g_bufB[(size_t)M_ * H4_];
__device__ float g_bufC[(size_t)M_ * NH_];
__device__ float g_bufD[(size_t)M_ * NH_];
__device__ uint32_t g_hA[2 * B_ * NC_];
__device__ uint32_t g_hB[2 * B_ * NC_];
__device__ unsigned g_bar_count;
__device__ unsigned g_bar_sense;

__device__ __forceinline__ float warpSum(float v) {
#pragma unroll
    for (int o = 16; o > 0; o >>= 1) v += __shfl_xor_sync(0xffffffffu, v, o);
    return v;
}
__device__ __forceinline__ float warpMax(float v) {
#pragma unroll
    for (int o = 16; o > 0; o >>= 1) v = fmaxf(v, __shfl_xor_sync(0xffffffffu, v, o));
    return v;
}
__device__ __forceinline__ float blockSum(float v, float* sh) {
    int lane = threadIdx.x & 31, w = threadIdx.x >> 5;
    v = warpSum(v);
    if (lane == 0) sh[w] = v;
    __syncthreads();
    if (w == 0) {
        float r = (lane < 8) ? sh[lane] : 0.f;
        r = warpSum(r);
        if (lane == 0) sh[0] = r;
    }
    __syncthreads();
    float r = sh[0];
    __syncthreads();
    return r;
}
__device__ __forceinline__ float blockMax(float v, float* sh) {
    int lane = threadIdx.x & 31, w = threadIdx.x >> 5;
    v = warpMax(v);
    if (lane == 0) sh[w] = v;
    __syncthreads();
    if (w == 0) {
        float r = (lane < 8) ? sh[lane] : -3.0e38f;
        r = warpMax(r);
        if (lane == 0) sh[0] = r;
    }
    __syncthreads();
    float r = sh[0];
    __syncthreads();
    return r;
}

__device__ __forceinline__ uint32_t f2tf32(float f) {
    uint32_t r;
    asm("cvt.rna.tf32.f32 %0, %1;" : "=r"(r) : "f"(f));
    return r;
}

__device__ __forceinline__ void mma_tf32(float* c, const uint32_t* a, const uint32_t* b) {
    asm volatile(
        "mma.sync.aligned.m16n8k8.row.col.f32.tf32.tf32.f32 "
        "{%0,%1,%2,%3}, {%4,%5,%6,%7}, {%8,%9}, {%0,%1,%2,%3};"
        : "+f"(c[0]), "+f"(c[1]), "+f"(c[2]), "+f"(c[3])
        : "r"(a[0]), "r"(a[1]), "r"(a[2]), "r"(a[3]), "r"(b[0]), "r"(b[1]));
}

// ---- tf32 tensor-core GEMM, cp.async double-buffered (R11) ----
#define GA_(st, r, c) gsm_[((st) * 128 + (r)) * 36 + (c)]
#define GB_(st, r, c) gsm_[(2 * 128 * 36) + ((st) * 128 + (r)) * 36 + (c)]
#define GEMM_SMEM (4 * 128 * 36 * 4)

__global__ __launch_bounds__(256, 2) void gemm_tf32(
    const float* __restrict__ A, const float* __restrict__ W,
    float* __restrict__ C, const float* __restrict__ bias1,
    const float* __restrict__ bias2, int M, int N, int K)
{
    extern __shared__ float gsm_[];
    int tid = threadIdx.x;
    int lane = tid & 31, warp = tid >> 5;
    int wm = warp >> 2, wn = warp & 3;
    int lr = lane >> 2, lc = lane & 3;
    int bm = blockIdx.y * 128, bn = blockIdx.x * 128;
    int ldrow = tid >> 3;
    int ldc4 = (tid & 7) << 2;

    float acc[4][4][4];
#pragma unroll
    for (int mt = 0; mt < 4; mt++)
#pragma unroll
        for (int nt = 0; nt < 4; nt++)
#pragma unroll
            for (int q = 0; q < 4; q++) acc[mt][nt][q] = 0.f;

    int niter = K >> 5;

#pragma unroll
    for (int i = 0; i < 4; i++) {
        int row = ldrow + (i << 5);
        uint32_t da = (uint32_t)__cvta_generic_to_shared(&GA_(0, row, ldc4));
        asm volatile("cp.async.cg.shared.global [%0], [%1], 16;"
                     :: "r"(da), "l"(A + (size_t)(bm + row) * K + ldc4));
        uint32_t db = (uint32_t)__cvta_generic_to_shared(&GB_(0, row, ldc4));
        asm volatile("cp.async.cg.shared.global [%0], [%1], 16;"
                     :: "r"(db), "l"(W + (size_t)(bn + row) * K + ldc4));
    }
    asm volatile("cp.async.commit_group;");

    for (int it = 0; it < niter; ++it) {
        int cur = it & 1;
        if (it + 1 < niter) {
            int nxt = cur ^ 1;
            int k0 = (it + 1) << 5;
#pragma unroll
            for (int i = 0; i < 4; i++) {
                int row = ldrow + (i << 5);
                uint32_t da = (uint32_t)__cvta_generic_to_shared(&GA_(nxt, row, ldc4));
                asm volatile("cp.async.cg.shared.global [%0], [%1], 16;"
                             :: "r"(da), "l"(A + (size_t)(bm + row) * K + k0 + ldc4));
                uint32_t db = (uint32_t)__cvta_generic_to_shared(&GB_(nxt, row, ldc4));
                asm volatile("cp.async.cg.shared.global [%0], [%1], 16;"
                             :: "r"(db), "l"(W + (size_t)(bn + row) * K + k0 + ldc4));
            }
            asm volatile("cp.async.commit_group;");
            asm volatile("cp.async.wait_group 1;" ::: "memory");
        } else {
            asm volatile("cp.async.wait_group 0;" ::: "memory");
        }
        __syncthreads();

#pragma unroll
        for (int ks = 0; ks < 4; ks++) {
            int kc = ks << 3;
            uint32_t af[4][4], bf[4][2];
#pragma unroll
            for (int mt = 0; mt < 4; mt++) {
                int rb = wm * 64 + mt * 16;
                af[mt][0] = f2tf32(GA_(cur, rb + lr, kc + lc));
                af[mt][1] = f2tf32(GA_(cur, rb + lr + 8, kc + lc));
                af[mt][2] = f2tf32(GA_(cur, rb + lr, kc + lc + 4));
                af[mt][3] = f2tf32(GA_(cur, rb + lr + 8, kc + lc + 4));
            }
#pragma unroll
            for (int nt = 0; nt < 4; nt++) {
                int nb = wn * 32 + nt * 8;
                bf[nt][0] = f2tf32(GB_(cur, nb + lr, kc + lc));
                bf[nt][1] = f2tf32(GB_(cur, nb + lr, kc + lc + 4));
            }
#pragma unroll
            for (int mt = 0; mt < 4; mt++)
#pragma unroll
                for (int nt = 0; nt < 4; nt++)
                    mma_tf32(acc[mt][nt], af[mt], bf[nt]);
        }
        __syncthreads();
    }

#pragma unroll
    for (int nt = 0; nt < 4; nt++) {
        int col = bn + wn * 32 + nt * 8 + (lc << 1);
        float b0 = bias1 ? bias1[col] : 0.f;
        float b1 = bias1 ? bias1[col + 1] : 0.f;
        if (bias2) { b0 += bias2[col]; b1 += bias2[col + 1]; }
#pragma unroll
        for (int mt = 0; mt < 4; mt++) {
            int row = bm + wm * 64 + mt * 16 + lr;
            float2 v0 = make_float2(acc[mt][nt][0] + b0, acc[mt][nt][1] + b1);
            float2 v1 = make_float2(acc[mt][nt][2] + b0, acc[mt][nt][3] + b1);
            *(float2*)(C + (size_t)row * N + col) = v0;
            *(float2*)(C + (size_t)(row + 8) * N + col) = v1;
        }
    }
}

// LayerNorm + LeakyReLU (+ pad-mask zero) in place
__global__ __launch_bounds__(256) void ln_lrelu(
    float* __restrict__ X, const float* __restrict__ g,
    const float* __restrict__ be, const int* __restrict__ lens)
{
    __shared__ float sh[8];
    int row = blockIdx.x;
    float* x = X + (size_t)row * NH_;
    int tid = threadIdx.x;
    float v[4], s = 0.f, ss = 0.f;
#pragma unroll
    for (int i = 0; i < 4; i++) {
        float t = x[tid + (i << 8)];
        v[i] = t; s += t; ss += t * t;
    }
    float S = blockSum(s, sh);
    float SS = blockSum(ss, sh);
    float mean = S * (1.f / NH_);
    float inv = rsqrtf(SS * (1.f / NH_) - mean * mean + 1e-5f);
    bool z = false;
    if (lens) z = ((row & (T_ - 1)) >= lens[row >> 9]);
#pragma unroll
    for (int i = 0; i < 4; i++) {
        int c = tid + (i << 8);
        float y = (v[i] - mean) * inv * g[c] + be[c];
        y = (y >= 0.f) ? y : 0.01f * y;
        x[c] = z ? 0.f : y;
    }
}

// ---- persistent bidirectional LSTM layer, tensor-core, 8-way K-split m32n32 ----
// 128 CTAs = 2 dirs x 64 chunks (8 hidden cols). 256 thr = 8 warps; warp p owns
// k in [64p, 64p+64) and computes the full 32b x 32n partial there.
// Partials summed in the cell phase from gsm (stride-34 padded).
#define LS_STRIDE 520
#define LS_H_OFF  (32 * LS_STRIDE)
#define LS_G_OFF  (64 * LS_STRIDE)
#define LSTM_SMEM ((64 * LS_STRIDE + 8 * 1088) * 4)

__device__ __forceinline__ float fast_sigmoid(float x) {
    return __fdividef(1.f, 1.f + __expf(-x));
}
__device__ __forceinline__ float fast_tanh(float x) {
    return __fdividef(2.f, 1.f + __expf(-2.f * x)) - 1.f;
}

__global__ __launch_bounds__(256) void lstm_layer(
    const float* __restrict__ xpf, const float* __restrict__ xpb,
    const float* __restrict__ whh,
    uint32_t* __restrict__ hA, uint32_t* __restrict__ hB,
    float* __restrict__ hcat)
{
    extern __shared__ float sm[];
    uint32_t* Wsm = (uint32_t*)sm;                  // [32 n][520] tf32, k-permuted
    uint32_t* hsp = (uint32_t*)(sm + LS_H_OFF);     // [32 b][520] tf32, k-permuted
    float*    gsm = sm + LS_G_OFF;                  // [8 part][32 b][34 pad(32 n)]
    __shared__ unsigned sh_base;

    int dir = blockIdx.x >> 6;
    int j0 = (blockIdx.x & 63) << 3;
    const float* xp = dir ? xpb : xpf;
    const float* W = whh + (size_t)dir * H4_ * NC_;
    int tid = threadIdx.x;
    int part = tid >> 5, lane = tid & 31;
    int lr = lane >> 2, lc = lane & 3;
    int koff = part << 6;                  // 64*part

    // cache + convert + permute whh slice (32 gate-cols x 512 k)
    for (int f = tid; f < 32 * 512; f += 256) {
        int n = f >> 9, k = f & 511;
        int g_ = n >> 3, jj = n & 7;
        float wv = W[(size_t)(g_ * NC_ + j0 + jj) * NC_ + k];
        int kp = (k & ~7) | ((k & 3) << 1) | ((k >> 2) & 1);
        Wsm[n * LS_STRIDE + kp] = f2tf32(wv);
    }
    if (tid == 0) sh_base = *(volatile unsigned*)&g_bar_sense;
    __syncthreads();
    unsigned base = sh_base;

    float creg = 0.f;
    int eb = tid >> 3, ej = tid & 7;       // cell element: batch, jj

    const uint32_t* hr = hsp + lr * LS_STRIDE + koff + 2 * lc;
    float* gw = gsm + part * 1088;

    for (int s = 0; s < T_; ++s) {
        int t = dir ? (T_ - 1 - s) : s;
        // xp prefetch in cell layout (per-thread, 4 gates) — independent of h
        float xg[4];
        {
            const float* xb = xp + ((size_t)eb * T_ + t) * H4_ + j0 + ej;
#pragma unroll
            for (int g = 0; g < 4; g++) xg[g] = xb[g * NC_];
        }
        if (s > 0) {
            const uint32_t* hin = ((s & 1) ? hB : hA) + dir * B_ * NC_;
            // stage full h tile (tf32 + permuted): 4096 uint4 over 256 threads
#pragma unroll
            for (int i = 0; i < 16; i++) {
                int idx = tid + (i << 8);
                int row = idx >> 7;
                int c4 = (idx & 127) << 2;
                uint4 v = *(const uint4*)(hin + row * NC_ + c4);
                *(uint4*)(hsp + row * LS_STRIDE + c4) = v;
            }
            __syncthreads();

            float acc[2][4][4];
#pragma unroll
            for (int mh = 0; mh < 2; mh++)
#pragma unroll
                for (int nt = 0; nt < 4; nt++)
#pragma unroll
                    for (int q = 0; q < 4; q++) acc[mh][nt][q] = 0.f;

#pragma unroll
            for (int kc = 0; kc < 64; kc += 8) {
                uint2 p0 = *(const uint2*)(hr + kc);
                uint2 p1 = *(const uint2*)(hr + 8 * LS_STRIDE + kc);
                uint2 p2 = *(const uint2*)(hr + 16 * LS_STRIDE + kc);
                uint2 p3 = *(const uint2*)(hr + 24 * LS_STRIDE + kc);
                uint32_t A0[4] = {p0.x, p1.x, p0.y, p1.y};
                uint32_t A1[4] = {p2.x, p3.x, p2.y, p3.y};
#pragma unroll
                for (int nt = 0; nt < 4; nt++) {
                    uint2 bv = *(const uint2*)(Wsm + (nt * 8 + lr) * LS_STRIDE
                                               + koff + kc + 2 * lc);
                    uint32_t Bf[2] = {bv.x, bv.y};
                    mma_tf32(acc[0][nt], A0, Bf);
                    mma_tf32(acc[1][nt], A1, Bf);
                }
            }
            // write partials: gsm[part][row][col], stride 34 (conflict-free)
#pragma unroll
            for (int mh = 0; mh < 2; mh++)
#pragma unroll
                for (int nt = 0; nt < 4; nt++) {
                    int r0 = mh * 16 + lr;
                    int c0 = nt * 8 + 2 * lc;
                    *(float2*)(gw + r0 * 34 + c0) =
                        make_float2(acc[mh][nt][0], acc[mh][nt][1]);
                    *(float2*)(gw + (r0 + 8) * 34 + c0) =
                        make_float2(acc[mh][nt][2], acc[mh][nt][3]);
                }
        }
        __syncthreads();

        // cell update: one element per thread; sum 8 K-partials per gate
        uint32_t* hout = ((s & 1) ? hA : hB) + dir * B_ * NC_;
        {
            float gi = xg[0], gf = xg[1], gg = xg[2], go = xg[3];
            if (s > 0) {
                const float* gp = gsm + eb * 34 + ej;
#pragma unroll
                for (int p = 0; p < 8; p++) {
                    gi += gp[p * 1088];
                    gf += gp[p * 1088 + 8];
                    gg += gp[p * 1088 + 16];
                    go += gp[p * 1088 + 24];
                }
            }
            float fi = fast_sigmoid(gi);
            float ff = fast_sigmoid(gf);
            float fo = fast_sigmoid(go);
            float cn = ff * creg + fi * fast_tanh(gg);
            float hv = fo * fast_tanh(cn);
            creg = cn;
            int kp = j0 + (((ej & 3) << 1) | (ej >> 2));
            hout[eb * NC_ + kp] = f2tf32(hv);
            hcat[((size_t)eb * T_ + t) * NH_ + dir * NC_ + j0 + ej] = hv;
        }
        __syncthreads();   // all h writes done before arrival signal

        // grid-wide barrier (sense-reversing, wrap-safe)
        if (tid == 0) {
            unsigned target = base + (unsigned)s + 1u;
            __threadfence();
            unsigned old = atomicAdd(&g_bar_count, 1u);
            if (old == 127u) {
                atomicExch(&g_bar_count, 0u);
                __threadfence();
                atomicExch(&g_bar_sense, target);
            } else {
                while ((int)(*(volatile unsigned*)&g_bar_sense - target) < 0) { }
                __threadfence();
            }
        }
        __syncthreads();
    }
}

// attention pool + classifier, one CTA per batch
__global__ __launch_bounds__(256) void attn_out(
    const float* __restrict__ H, const int* __restrict__ lens,
    const float* __restrict__ w_u, const float* __restrict__ b_u,
    const float* __restrict__ Wc, const float* __restrict__ bc,
    float* __restrict__ out)
{
    __shared__ float sc[T_];
    __shared__ float pooled[NH_];
    __shared__ float red[8];
    int b = blockIdx.x;
    int tid = threadIdx.x, lane = tid & 31, w = tid >> 5;
    int len = lens[b];
    const float* Hb = H + (size_t)b * T_ * NH_;

    for (int t = w; t < T_; t += 8) {
        const float* hp = Hb + (size_t)t * NH_;
        float s = 0.f;
        for (int d = lane; d < NH_; d += 32) s += hp[d] * w_u[d];
        s = warpSum(s);
        if (lane == 0) sc[t] = s + b_u[0];
    }
    __syncthreads();

    float m = -3.0e38f;
    for (int t = tid; t < len; t += 256) m = fmaxf(m, sc[t]);
    m = blockMax(m, red);

    float ps = 0.f;
    for (int t = tid; t < T_; t += 256) {
        float e = (t < len) ? expf(sc[t] - m) : 0.f;
        sc[t] = e; ps += e;
    }
    float S = blockSum(ps, red);
    float inv = 1.f / S;

    {
        float a0 = 0.f, a1 = 0.f, a2 = 0.f, a3 = 0.f;
        for (int t = 0; t < len; ++t) {
            float al = sc[t];
            const float* hp = Hb + (size_t)t * NH_ + tid;
            a0 += al * hp[0];
            a1 += al * hp[256];
            a2 += al * hp[512];
            a3 += al * hp[768];
        }
        pooled[tid]       = a0 * inv;
        pooled[tid + 256] = a1 * inv;
        pooled[tid + 512] = a2 * inv;
        pooled[tid + 768] = a3 * inv;
    }
    __syncthreads();

    {
        const float* wc = Wc + (size_t)w * NH_;
        float s = 0.f;
        for (int d = lane; d < NH_; d += 32) s += pooled[d] * wc[d];
        s = warpSum(s);
        if (lane == 0) out[b * NOUT_ + w] = s + bc[w];
    }
}

extern "C" void kernel_launch(void* const* d_in, const int* in_sizes, int n_in,
                              void* d_out, int out_size)
{
    const float* x    = (const float*)d_in[0];
    const int*   lens = (const int*)d_in[1];
    const float* W1   = (const float*)d_in[2];
    const float* b1   = (const float*)d_in[3];
    const float* g1   = (const float*)d_in[4];
    const float* be1  = (const float*)d_in[5];
    const float* W2   = (const float*)d_in[6];
    const float* b2   = (const float*)d_in[7];
    const float* g2   = (const float*)d_in[8];
    const float* be2  = (const float*)d_in[9];
    const float* wih  = (const float*)d_in[10];
    const float* whh  = (const float*)d_in[11];
    const float* bih  = (const float*)d_in[12];
    const float* bhh  = (const float*)d_in[13];
    const float* w_u  = (const float*)d_in[14];
    const float* b_u  = (const float*)d_in[15];
    const float* Wc   = (const float*)d_in[16];
    const float* bc   = (const float*)d_in[17];
    float* out = (float*)d_out;
    (void)in_sizes; (void)n_in; (void)out_size;

    float *bufA, *bufB, *bufC, *bufD;
    uint32_t *hA, *hB;
    cudaGetSymbolAddress((void**)&bufA, g_bufA);
    cudaGetSymbolAddress((void**)&bufB, g_bufB);
    cudaGetSymbolAddress((void**)&bufC, g_bufC);
    cudaGetSymbolAddress((void**)&bufD, g_bufD);
    cudaGetSymbolAddress((void**)&hA, g_hA);
    cudaGetSymbolAddress((void**)&hB, g_hB);

    cudaFuncSetAttribute(lstm_layer, cudaFuncAttributeMaxDynamicSharedMemorySize,
                         LSTM_SMEM);
    cudaFuncSetAttribute(gemm_tf32, cudaFuncAttributeMaxDynamicSharedMemorySize,
                         GEMM_SMEM);

    dim3 blk(256);
    dim3 gMLP(NH_ / 128, M_ / 128);
    dim3 gXP(H4_ / 128, M_ / 128);

    gemm_tf32<<<gMLP, blk, GEMM_SMEM>>>(x, W1, bufD, b1, nullptr, M_, NH_, FD_);
    ln_lrelu<<<M_, blk>>>(bufD, g1, be1, nullptr);
    gemm_tf32<<<gMLP, blk, GEMM_SMEM>>>(bufD, W2, bufC, b2, nullptr, M_, NH_, NH_);
    ln_lrelu<<<M_, blk>>>(bufC, g2, be2, lens);

    for (int layer = 0; layer < 2; ++layer) {
        const float* inbuf = (layer == 0) ? bufC : bufD;
        float* hcat = (layer == 0) ? bufD : bufC;
        size_t wo = (size_t)layer * 2 * H4_ * NH_;
        size_t ho = (size_t)layer * 2 * H4_ * NC_;
        size_t bo = (size_t)layer * 2 * H4_;

        gemm_tf32<<<gXP, blk, GEMM_SMEM>>>(inbuf, wih + wo, bufA,
                                           bih + bo, bhh + bo, M_, H4_, NH_);
        gemm_tf32<<<gXP, blk, GEMM_SMEM>>>(inbuf, wih + wo + (size_t)H4_ * NH_, bufB,
                                           bih + bo + H4_, bhh + bo + H4_, M_, H4_, NH_);

        lstm_layer<<<128, 256, LSTM_SMEM>>>(bufA, bufB, whh + ho, hA, hB, hcat);
    }

    attn_out<<<B_, blk>>>(bufC, lens, w_u, b_u, Wc, bc, out);
}